// round 2
// baseline (speedup 1.0000x reference)
#include <cuda_runtime.h>
#include <math.h>

#define Bb 8
#define Nn 16384
#define Dd 768
#define Rr 3
#define NEx 4
#define Hh 128
#define NBLK 128   // blocks per batch in proj_down

// ---- scratch (device globals; no allocations allowed) ----
__device__ float g_xr[Bb * Nn * Rr];        // (B, N, R)
__device__ float g_mixed[Bb * Nn * Rr];     // (B, N, R)
__device__ float g_partial[Bb * NBLK * Rr]; // per-block partial sums of xr
__device__ float g_G[Bb * NEx];             // gating weights

// ============================================================
// K1: xr = x @ Wd + bd  (warp per token), + deterministic partial sums
// grid (NBLK, B), 256 threads
// ============================================================
__global__ __launch_bounds__(256) void k_proj_down(const float* __restrict__ x,
                                                   const float* __restrict__ Wd,
                                                   const float* __restrict__ bd) {
    __shared__ float sW[Dd * Rr];
    __shared__ float red[8][3];
    const int b = blockIdx.y, blk = blockIdx.x;
    for (int i = threadIdx.x; i < Dd * Rr; i += 256) sW[i] = Wd[i];
    __syncthreads();
    const int warp = threadIdx.x >> 5, lane = threadIdx.x & 31;

    // per-lane register cache of Wd columns for this lane's fixed d-slices
    float4 w0[6], w1[6], w2[6];
#pragma unroll
    for (int it = 0; it < 6; it++) {
        int d = (lane + 32 * it) * 4;
        w0[it] = make_float4(sW[(d+0)*3+0], sW[(d+1)*3+0], sW[(d+2)*3+0], sW[(d+3)*3+0]);
        w1[it] = make_float4(sW[(d+0)*3+1], sW[(d+1)*3+1], sW[(d+2)*3+1], sW[(d+3)*3+1]);
        w2[it] = make_float4(sW[(d+0)*3+2], sW[(d+1)*3+2], sW[(d+2)*3+2], sW[(d+3)*3+2]);
    }
    const float b0 = bd[0], b1 = bd[1], b2 = bd[2];
    float p0 = 0.f, p1 = 0.f, p2 = 0.f;

    const int t0 = blk * (Nn / NBLK);
    for (int t = t0 + warp; t < t0 + (Nn / NBLK); t += 8) {
        const float4* xt = (const float4*)(x + ((size_t)b * Nn + t) * Dd);
        float a0 = 0.f, a1 = 0.f, a2 = 0.f;
#pragma unroll
        for (int it = 0; it < 6; it++) {
            float4 v = xt[lane + 32 * it];
            a0 += v.x*w0[it].x + v.y*w0[it].y + v.z*w0[it].z + v.w*w0[it].w;
            a1 += v.x*w1[it].x + v.y*w1[it].y + v.z*w1[it].z + v.w*w1[it].w;
            a2 += v.x*w2[it].x + v.y*w2[it].y + v.z*w2[it].z + v.w*w2[it].w;
        }
#pragma unroll
        for (int off = 16; off; off >>= 1) {
            a0 += __shfl_xor_sync(0xffffffffu, a0, off);
            a1 += __shfl_xor_sync(0xffffffffu, a1, off);
            a2 += __shfl_xor_sync(0xffffffffu, a2, off);
        }
        if (lane == 0) {
            a0 += b0; a1 += b1; a2 += b2;
            float* o = g_xr + ((size_t)b * Nn + t) * 3;
            o[0] = a0; o[1] = a1; o[2] = a2;
            p0 += a0; p1 += a1; p2 += a2;
        }
    }
    if (lane == 0) { red[warp][0] = p0; red[warp][1] = p1; red[warp][2] = p2; }
    __syncthreads();
    if (threadIdx.x == 0) {
        float s0 = 0.f, s1 = 0.f, s2 = 0.f;
#pragma unroll
        for (int w = 0; w < 8; w++) { s0 += red[w][0]; s1 += red[w][1]; s2 += red[w][2]; }
        float* o = g_partial + (b * NBLK + blk) * 3;
        o[0] = s0; o[1] = s1; o[2] = s2;
    }
}

// ============================================================
// K2: gating (mean -> Hg/Hns -> noisy logits -> top-2 -> softmax)
// single block of 32 threads, fully deterministic
// ============================================================
__global__ void k_gate(const float* __restrict__ noise,
                       const float* __restrict__ Wg,
                       const float* __restrict__ Wn) {
    __shared__ float sxa[Bb][Rr];
    const int t = threadIdx.x;
    if (t < Bb * Rr) {
        int b = t / 3, r = t % 3;
        float s = 0.f;
        for (int k = 0; k < NBLK; k++) s += g_partial[(b * NBLK + k) * 3 + r];
        sxa[b][r] = s * (1.0f / Nn);
    }
    __syncthreads();
    if (t < Bb) {
        float x0 = sxa[t][0], x1 = sxa[t][1], x2 = sxa[t][2];
        float hl[NEx];
#pragma unroll
        for (int e = 0; e < NEx; e++) {
            float hg = x0 * Wg[e] + x1 * Wg[NEx + e] + x2 * Wg[2 * NEx + e];
            float z  = x0 * Wn[e] + x1 * Wn[NEx + e] + x2 * Wn[2 * NEx + e];
            float sp = fmaxf(z, 0.f) + log1pf(expf(-fabsf(z)));  // stable softplus (== jax)
            hl[e] = hg + noise[t * NEx + e] * sp;
        }
        int i1 = 0;
#pragma unroll
        for (int e = 1; e < NEx; e++) if (hl[e] > hl[i1]) i1 = e;
        int i2 = -1;
#pragma unroll
        for (int e = 0; e < NEx; e++) if (e != i1 && (i2 < 0 || hl[e] > hl[i2])) i2 = e;
        float e2  = expf(hl[i2] - hl[i1]);
        float inv = 1.f / (1.f + e2);
#pragma unroll
        for (int e = 0; e < NEx; e++)
            g_G[t * NEx + e] = (e == i1) ? inv : ((e == i2) ? e2 * inv : 0.f);
    }
}

// ============================================================
// K3: experts. One block per (b, r) channel. All resizes are exact
// 2-tap averages (frac = 0.5) down / 4-tap clamped bilinear up.
// dwconv 3x3 zero-padded (correlation, no flip), + bias.
// mixed accumulated in global (block-private channel, no atomics needed).
// ============================================================
__global__ __launch_bounds__(256) void k_experts(const float* __restrict__ dwk,
                                                 const float* __restrict__ dwb) {
    __shared__ float sD[64 * 64];
    __shared__ float sC[64 * 64];
    __shared__ float sK[9];
    __shared__ float sBias;
    __shared__ float sg[4];
    const int b = blockIdx.x / 3, r = blockIdx.x % 3;
    if (threadIdx.x < 9)  sK[threadIdx.x] = dwk[r * 9 + threadIdx.x];
    if (threadIdx.x == 9) sBias = dwb[r];
    if (threadIdx.x >= 16 && threadIdx.x < 20) sg[threadIdx.x - 16] = g_G[b * 4 + (threadIdx.x - 16)];
    __syncthreads();

    const float* __restrict__ A = g_xr + (size_t)b * Nn * 3 + r;   // A[(i*128+j)*3]
    float* __restrict__ M = g_mixed + (size_t)b * Nn * 3 + r;      // M[p*3]
    const float bias = sBias;

    // ---- scale 1.0: dwconv at full res, weighted write ----
    {
        const float g0 = sg[0];
        for (int p = threadIdx.x; p < Hh * Hh; p += 256) {
            int i = p >> 7, j = p & 127;
            float s = bias;
#pragma unroll
            for (int dy = -1; dy <= 1; dy++) {
                int ii = i + dy;
                if (ii < 0 || ii > 127) continue;
#pragma unroll
                for (int dx = -1; dx <= 1; dx++) {
                    int jj = j + dx;
                    if (jj < 0 || jj > 127) continue;
                    s += sK[(dy + 1) * 3 + (dx + 1)] * A[(ii * 128 + jj) * 3];
                }
            }
            M[p * 3] = g0 * s;
        }
    }
    __syncthreads();

    // ---- scales 0.5, 0.25, 0.125 ----
#pragma unroll 1
    for (int sc = 1; sc <= 3; sc++) {
        const int f = 1 << sc;
        const int m = 128 >> sc;
        const int o = (sc == 1) ? 0 : (sc == 2 ? 1 : 3);  // first-tap offset of the 2-tap average
        const float g = sg[sc];
        const float invf = 1.0f / (float)f;

        // downsample: avg of 2x2 picks at (f*i+o .. +1, f*j+o .. +1) — always in range
        for (int p = threadIdx.x; p < m * m; p += 256) {
            int i = p / m, j = p - i * m;
            const float* base = A + ((f * i + o) * 128 + (f * j + o)) * 3;
            sD[p] = 0.25f * (base[0] + base[3] + base[128 * 3] + base[129 * 3]);
        }
        __syncthreads();

        // dwconv 3x3 zero-padded on m x m
        for (int p = threadIdx.x; p < m * m; p += 256) {
            int i = p / m, j = p - i * m;
            float s = bias;
#pragma unroll
            for (int dy = -1; dy <= 1; dy++) {
                int ii = i + dy;
                if (ii < 0 || ii >= m) continue;
#pragma unroll
                for (int dx = -1; dx <= 1; dx++) {
                    int jj = j + dx;
                    if (jj < 0 || jj >= m) continue;
                    s += sK[(dy + 1) * 3 + (dx + 1)] * sD[ii * m + jj];
                }
            }
            sC[p] = s;
        }
        __syncthreads();

        // upsample (half-pixel bilinear, clamped == jax edge renorm) + accumulate
        for (int p = threadIdx.x; p < Hh * Hh; p += 256) {
            int oi = p >> 7, oj = p & 127;
            float sy = (oi + 0.5f) * invf - 0.5f;
            float sx = (oj + 0.5f) * invf - 0.5f;
            int y0 = (int)floorf(sy); float fy = sy - (float)y0;
            int x0 = (int)floorf(sx); float fx = sx - (float)x0;
            int y0c = max(y0, 0), y1c = min(y0 + 1, m - 1);
            int x0c = max(x0, 0), x1c = min(x0 + 1, m - 1);
            float v00 = sC[y0c * m + x0c], v01 = sC[y0c * m + x1c];
            float v10 = sC[y1c * m + x0c], v11 = sC[y1c * m + x1c];
            float v = (1.f - fy) * ((1.f - fx) * v00 + fx * v01)
                    +        fy  * ((1.f - fx) * v10 + fx * v11);
            M[p * 3] += g * v;
        }
        __syncthreads();
    }
}

// ============================================================
// K4: out = x + mixed @ Wu + bu   (float4 streaming)
// ============================================================
__global__ __launch_bounds__(256) void k_proj_up(const float* __restrict__ x,
                                                 const float* __restrict__ Wu,
                                                 const float* __restrict__ bu,
                                                 float* __restrict__ out) {
    __shared__ float4 sW4[3 * 192];
    __shared__ float4 sB4[192];
    {
        float* sWf = (float*)sW4;
        float* sBf = (float*)sB4;
        for (int i = threadIdx.x; i < 3 * Dd; i += 256) sWf[i] = Wu[i];
        for (int i = threadIdx.x; i < Dd; i += 256) sBf[i] = bu[i];
    }
    __syncthreads();
    const size_t total = (size_t)Bb * Nn * (Dd / 4);
    const size_t stride = (size_t)gridDim.x * 256;
    for (size_t idx = (size_t)blockIdx.x * 256 + threadIdx.x; idx < total; idx += stride) {
        size_t token = idx / 192;
        int q = (int)(idx - token * 192);
        const float* __restrict__ mp = g_mixed + token * 3;
        float m0 = __ldg(mp + 0), m1 = __ldg(mp + 1), m2 = __ldg(mp + 2);
        float4 xv = ((const float4*)x)[idx];
        float4 wu0 = sW4[q], wu1 = sW4[192 + q], wu2 = sW4[384 + q];
        float4 bb  = sB4[q];
        float4 ov;
        ov.x = xv.x + bb.x + m0 * wu0.x + m1 * wu1.x + m2 * wu2.x;
        ov.y = xv.y + bb.y + m0 * wu0.y + m1 * wu1.y + m2 * wu2.y;
        ov.z = xv.z + bb.z + m0 * wu0.z + m1 * wu1.z + m2 * wu2.z;
        ov.w = xv.w + bb.w + m0 * wu0.w + m1 * wu1.w + m2 * wu2.w;
        ((float4*)out)[idx] = ov;
    }
}

// ============================================================
// launch
// ============================================================
extern "C" void kernel_launch(void* const* d_in, const int* in_sizes, int n_in,
                              void* d_out, int out_size) {
    const float* x     = (const float*)d_in[0];
    const float* noise = (const float*)d_in[1];
    const float* Wd    = (const float*)d_in[2];
    const float* bd    = (const float*)d_in[3];
    const float* Wu    = (const float*)d_in[4];
    const float* bu    = (const float*)d_in[5];
    const float* Wg    = (const float*)d_in[6];
    const float* Wn    = (const float*)d_in[7];
    const float* dwk   = (const float*)d_in[8];
    const float* dwb   = (const float*)d_in[9];
    float* out = (float*)d_out;

    k_proj_down<<<dim3(NBLK, Bb), 256>>>(x, Wd, bd);
    k_gate<<<1, 32>>>(noise, Wg, Wn);
    k_experts<<<Bb * Rr, 256>>>(dwk, dwb);
    k_proj_up<<<2368, 256>>>(x, Wu, bu, out);
}

// round 3
// speedup vs baseline: 1.1858x; 1.1858x over previous
#include <cuda_runtime.h>
#include <math.h>

#define Bb 8
#define Nn 16384
#define Dd 768
#define Rr 3
#define NEx 4
#define Hh 128
#define KBLK 64          // K1 blocks per batch
#define PLANE 16384      // floats per (b,r) plane
#define CHPLN 49152      // floats per batch (3 planes)

// ---- scratch (device globals; no allocations allowed) ----
__device__ float g_xr[Bb * Rr * PLANE];       // planar (B, R, N)
__device__ float g_mixed[Bb * Rr * PLANE];    // planar (B, R, N)
__device__ float g_up[3][Bb * Rr * PLANE];    // upsampled expert outputs, scales 1..3
__device__ float g_partial[Bb * KBLK * 8 * 3];// per-warp partial sums of xr
__device__ float g_G[Bb * NEx];               // gating weights

// ============================================================
// K1: xr = x @ Wd + bd. cp.async double-buffered 8-token groups.
// grid = Bb*KBLK = 512 blocks x 256 thr. Each block: 256 tokens = 32 groups.
// ============================================================
__device__ __forceinline__ void k1_issue(const float4* src, float* dstbuf, int tid) {
    unsigned dst = (unsigned)__cvta_generic_to_shared(dstbuf);
#pragma unroll
    for (int i = 0; i < 6; ++i) {
        asm volatile("cp.async.cg.shared.global [%0], [%1], 16;\n"
                     :: "r"(dst + (unsigned)(tid + 256 * i) * 16u),
                        "l"(src + tid + 256 * i));
    }
    asm volatile("cp.async.commit_group;\n");
}

__global__ __launch_bounds__(256, 2) void k_proj_down(const float* __restrict__ x,
                                                      const float* __restrict__ Wd,
                                                      const float* __restrict__ bd) {
    __shared__ float buf[2][8 * Dd];  // 48KB exactly
    const int b = blockIdx.x >> 6, blk = blockIdx.x & 63;
    const int tid = threadIdx.x, warp = tid >> 5, lane = tid & 31;

    // stage Wd through buf[0], pull per-lane weight slices into regs
    for (int i = tid; i < Dd * Rr; i += 256) buf[0][i] = Wd[i];
    __syncthreads();
    float4 w0[6], w1[6], w2[6];
#pragma unroll
    for (int it = 0; it < 6; ++it) {
        int d = (lane + 32 * it) * 4;
        w0[it] = make_float4(buf[0][(d+0)*3+0], buf[0][(d+1)*3+0], buf[0][(d+2)*3+0], buf[0][(d+3)*3+0]);
        w1[it] = make_float4(buf[0][(d+0)*3+1], buf[0][(d+1)*3+1], buf[0][(d+2)*3+1], buf[0][(d+3)*3+1]);
        w2[it] = make_float4(buf[0][(d+0)*3+2], buf[0][(d+1)*3+2], buf[0][(d+2)*3+2], buf[0][(d+3)*3+2]);
    }
    const float b0 = bd[0], b1 = bd[1], b2 = bd[2];
    __syncthreads();

    const int token0 = blk * 256;
    const float4* src = (const float4*)(x + ((size_t)b * Nn + token0) * Dd);

    k1_issue(src, buf[0], tid);
    k1_issue(src + 1536, buf[1], tid);

    float p0 = 0.f, p1 = 0.f, p2 = 0.f;
#pragma unroll 1
    for (int g = 0; g < 32; ++g) {
        if (g < 31) asm volatile("cp.async.wait_group 1;\n");
        else        asm volatile("cp.async.wait_group 0;\n");
        __syncthreads();

        const float4* tb = (const float4*)&buf[g & 1][warp * Dd];
        float a0 = 0.f, a1 = 0.f, a2 = 0.f;
#pragma unroll
        for (int it = 0; it < 6; ++it) {
            float4 v = tb[lane + 32 * it];
            a0 += v.x*w0[it].x + v.y*w0[it].y + v.z*w0[it].z + v.w*w0[it].w;
            a1 += v.x*w1[it].x + v.y*w1[it].y + v.z*w1[it].z + v.w*w1[it].w;
            a2 += v.x*w2[it].x + v.y*w2[it].y + v.z*w2[it].z + v.w*w2[it].w;
        }
#pragma unroll
        for (int off = 16; off; off >>= 1) {
            a0 += __shfl_xor_sync(0xffffffffu, a0, off);
            a1 += __shfl_xor_sync(0xffffffffu, a1, off);
            a2 += __shfl_xor_sync(0xffffffffu, a2, off);
        }
        if (lane == 0) {
            a0 += b0; a1 += b1; a2 += b2;
            int t = token0 + g * 8 + warp;
            g_xr[b * CHPLN + t]              = a0;
            g_xr[b * CHPLN + PLANE + t]      = a1;
            g_xr[b * CHPLN + 2 * PLANE + t]  = a2;
            p0 += a0; p1 += a1; p2 += a2;
        }
        __syncthreads();
        if (g + 2 < 32) k1_issue(src + (size_t)(g + 2) * 1536, buf[g & 1], tid);
    }
    if (lane == 0) {
        int pi = ((b * KBLK + blk) * 8 + warp) * 3;
        g_partial[pi] = p0; g_partial[pi + 1] = p1; g_partial[pi + 2] = p2;
    }
}

// ============================================================
// K2: gating. 1 block x 32 threads, fully deterministic.
// ============================================================
__global__ void k_gate(const float* __restrict__ noise,
                       const float* __restrict__ Wg,
                       const float* __restrict__ Wn) {
    __shared__ float sxa[Bb][Rr];
    const int t = threadIdx.x;
    if (t < Bb * Rr) {
        int b = t / 3, r = t % 3;
        float s = 0.f;
        for (int j = 0; j < KBLK * 8; ++j) s += g_partial[(b * KBLK * 8 + j) * 3 + r];
        sxa[b][r] = s * (1.0f / Nn);
    }
    __syncthreads();
    if (t < Bb) {
        float x0 = sxa[t][0], x1 = sxa[t][1], x2 = sxa[t][2];
        float hl[NEx];
#pragma unroll
        for (int e = 0; e < NEx; ++e) {
            float hg = x0 * Wg[e] + x1 * Wg[NEx + e] + x2 * Wg[2 * NEx + e];
            float z  = x0 * Wn[e] + x1 * Wn[NEx + e] + x2 * Wn[2 * NEx + e];
            float sp = fmaxf(z, 0.f) + log1pf(expf(-fabsf(z)));
            hl[e] = hg + noise[t * NEx + e] * sp;
        }
        int i1 = 0;
#pragma unroll
        for (int e = 1; e < NEx; ++e) if (hl[e] > hl[i1]) i1 = e;
        int i2 = -1;
#pragma unroll
        for (int e = 0; e < NEx; ++e) if (e != i1 && (i2 < 0 || hl[e] > hl[i2])) i2 = e;
        float e2  = expf(hl[i2] - hl[i1]);
        float inv = 1.f / (1.f + e2);
#pragma unroll
        for (int e = 0; e < NEx; ++e)
            g_G[t * NEx + e] = (e == i1) ? inv : ((e == i2) ? e2 * inv : 0.f);
    }
}

// ============================================================
// K3a: full-res dwconv, weighted by G[b][0], writes g_mixed.
// grid (8 tiles, 24 channels) x 256
// ============================================================
__global__ __launch_bounds__(256) void k_conv_full(const float* __restrict__ dwk,
                                                   const float* __restrict__ dwb) {
    const int ch = blockIdx.y, b = ch / 3, r = ch - b * 3;
    __shared__ float sK[9];
    __shared__ float sc0[2];
    if (threadIdx.x < 9) sK[threadIdx.x] = dwk[r * 9 + threadIdx.x];
    if (threadIdx.x == 9)  sc0[0] = dwb[r];
    if (threadIdx.x == 10) sc0[1] = g_G[b * 4];
    __syncthreads();
    const float bias = sc0[0], g0 = sc0[1];
    const float* __restrict__ A = g_xr + ch * PLANE;
    float* __restrict__ M = g_mixed + ch * PLANE;
    const int p0 = blockIdx.x * 2048;
    for (int p = p0 + threadIdx.x; p < p0 + 2048; p += 256) {
        int i = p >> 7, j = p & 127;
        float s = bias;
#pragma unroll
        for (int dy = -1; dy <= 1; ++dy) {
            int ii = i + dy;
            if (ii < 0 || ii > 127) continue;
#pragma unroll
            for (int dx = -1; dx <= 1; ++dx) {
                int jj = j + dx;
                if (jj < 0 || jj > 127) continue;
                s += sK[(dy + 1) * 3 + (dx + 1)] * A[ii * 128 + jj];
            }
        }
        M[p] = g0 * s;
    }
}

// ============================================================
// K3b: low-res expert scales. grid (24 channels, 3 scales) x 256.
// down(2-tap avg) -> conv3x3 -> up(bilinear, clamped) -> g_up[sc-1]
// ============================================================
template <int SC>
__device__ __forceinline__ void expert_scale(const float* __restrict__ A,
                                             float* __restrict__ U,
                                             float* sD, float* sC,
                                             const float* sK, float bias) {
    constexpr int f = 1 << SC;
    constexpr int m = 128 >> SC;
    constexpr int o = (SC == 1) ? 0 : (SC == 2 ? 1 : 3);
    constexpr float invf = 1.0f / (float)f;

    for (int p = threadIdx.x; p < m * m; p += 256) {
        int i = p / m, j = p - i * m;
        const float* base = A + (f * i + o) * 128 + (f * j + o);
        sD[p] = 0.25f * (base[0] + base[1] + base[128] + base[129]);
    }
    __syncthreads();
    for (int p = threadIdx.x; p < m * m; p += 256) {
        int i = p / m, j = p - i * m;
        float s = bias;
#pragma unroll
        for (int dy = -1; dy <= 1; ++dy) {
            int ii = i + dy;
            if (ii < 0 || ii >= m) continue;
#pragma unroll
            for (int dx = -1; dx <= 1; ++dx) {
                int jj = j + dx;
                if (jj < 0 || jj >= m) continue;
                s += sK[(dy + 1) * 3 + (dx + 1)] * sD[ii * m + jj];
            }
        }
        sC[p] = s;
    }
    __syncthreads();
    for (int p = threadIdx.x; p < Hh * Hh; p += 256) {
        int oi = p >> 7, oj = p & 127;
        float sy = (oi + 0.5f) * invf - 0.5f;
        float sx = (oj + 0.5f) * invf - 0.5f;
        int y0 = (int)floorf(sy); float fy = sy - (float)y0;
        int x0 = (int)floorf(sx); float fx = sx - (float)x0;
        int y0c = max(y0, 0), y1c = min(y0 + 1, m - 1);
        int x0c = max(x0, 0), x1c = min(x0 + 1, m - 1);
        float v00 = sC[y0c * m + x0c], v01 = sC[y0c * m + x1c];
        float v10 = sC[y1c * m + x0c], v11 = sC[y1c * m + x1c];
        U[p] = (1.f - fy) * ((1.f - fx) * v00 + fx * v01)
             +        fy  * ((1.f - fx) * v10 + fx * v11);
    }
}

__global__ __launch_bounds__(256) void k_expert_lo(const float* __restrict__ dwk,
                                                   const float* __restrict__ dwb) {
    __shared__ float sD[4096];
    __shared__ float sC[4096];
    __shared__ float sK[9];
    __shared__ float sBias;
    const int ch = blockIdx.x, r = ch % 3;
    const int sc = blockIdx.y + 1;
    if (threadIdx.x < 9) sK[threadIdx.x] = dwk[r * 9 + threadIdx.x];
    if (threadIdx.x == 9) sBias = dwb[r];
    __syncthreads();
    const float* A = g_xr + ch * PLANE;
    float* U = g_up[sc - 1] + ch * PLANE;
    if (sc == 1)      expert_scale<1>(A, U, sD, sC, sK, sBias);
    else if (sc == 2) expert_scale<2>(A, U, sD, sC, sK, sBias);
    else              expert_scale<3>(A, U, sD, sC, sK, sBias);
}

// ============================================================
// K3c: blend low-res scales into g_mixed. 384 blocks x 256 (float4 each).
// ============================================================
__global__ __launch_bounds__(256) void k_blend() {
    int idx = blockIdx.x * 256 + threadIdx.x;       // float4 index, [0, 98304)
    int b = idx / 12288;                            // 12288 float4 per batch
    float g1 = g_G[b * 4 + 1], g2 = g_G[b * 4 + 2], g3 = g_G[b * 4 + 3];
    float4 u1 = ((const float4*)g_up[0])[idx];
    float4 u2 = ((const float4*)g_up[1])[idx];
    float4 u3 = ((const float4*)g_up[2])[idx];
    float4* mp = (float4*)g_mixed + idx;
    float4 mv = *mp;
    mv.x += g1 * u1.x + g2 * u2.x + g3 * u3.x;
    mv.y += g1 * u1.y + g2 * u2.y + g3 * u3.y;
    mv.z += g1 * u1.z + g2 * u2.z + g3 * u3.z;
    mv.w += g1 * u1.w + g2 * u2.w + g3 * u3.w;
    *mp = mv;
}

// ============================================================
// K4: out = x + mixed @ Wu + bu. 2 float4 per thread-iter (never
// straddles a token: 192 float4/token is even). Streaming hints.
// ============================================================
__global__ __launch_bounds__(256) void k_proj_up(const float* __restrict__ x,
                                                 const float* __restrict__ Wu,
                                                 const float* __restrict__ bu,
                                                 float* __restrict__ out) {
    __shared__ float sW[Rr * Dd];
    __shared__ float sB[Dd];
    for (int i = threadIdx.x; i < Rr * Dd; i += 256) sW[i] = Wu[i];
    for (int i = threadIdx.x; i < Dd; i += 256) sB[i] = bu[i];
    __syncthreads();
    const int total = Bb * Nn * (Dd / 8);            // pairs of float4
    const int stride = gridDim.x * 256;
    for (int p = blockIdx.x * 256 + threadIdx.x; p < total; p += stride) {
        int tk = p / 96;                              // token (96 pairs/token)
        int q2 = (p - tk * 96) * 2;                   // float4 chunk within token
        int b  = tk >> 14;
        int t  = tk & (Nn - 1);
        const float* mp = g_mixed + b * CHPLN + t;
        float m0 = __ldg(mp), m1 = __ldg(mp + PLANE), m2 = __ldg(mp + 2 * PLANE);
        const float4* xp = (const float4*)x + (size_t)tk * 192 + q2;
        float4 xv0 = __ldcs(xp), xv1 = __ldcs(xp + 1);
        int d4 = q2 * 4;
        float4 a0 = *(const float4*)&sW[d4],          a0b = *(const float4*)&sW[d4 + 4];
        float4 a1 = *(const float4*)&sW[Dd + d4],     a1b = *(const float4*)&sW[Dd + d4 + 4];
        float4 a2 = *(const float4*)&sW[2*Dd + d4],   a2b = *(const float4*)&sW[2*Dd + d4 + 4];
        float4 bb = *(const float4*)&sB[d4],          bbb = *(const float4*)&sB[d4 + 4];
        float4 o0, o1;
        o0.x = xv0.x + bb.x + m0*a0.x + m1*a1.x + m2*a2.x;
        o0.y = xv0.y + bb.y + m0*a0.y + m1*a1.y + m2*a2.y;
        o0.z = xv0.z + bb.z + m0*a0.z + m1*a1.z + m2*a2.z;
        o0.w = xv0.w + bb.w + m0*a0.w + m1*a1.w + m2*a2.w;
        o1.x = xv1.x + bbb.x + m0*a0b.x + m1*a1b.x + m2*a2b.x;
        o1.y = xv1.y + bbb.y + m0*a0b.y + m1*a1b.y + m2*a2b.y;
        o1.z = xv1.z + bbb.z + m0*a0b.z + m1*a1b.z + m2*a2b.z;
        o1.w = xv1.w + bbb.w + m0*a0b.w + m1*a1b.w + m2*a2b.w;
        float4* op = (float4*)out + (size_t)tk * 192 + q2;
        __stcs(op, o0);
        __stcs(op + 1, o1);
    }
}

// ============================================================
// launch
// ============================================================
extern "C" void kernel_launch(void* const* d_in, const int* in_sizes, int n_in,
                              void* d_out, int out_size) {
    const float* x     = (const float*)d_in[0];
    const float* noise = (const float*)d_in[1];
    const float* Wd    = (const float*)d_in[2];
    const float* bd    = (const float*)d_in[3];
    const float* Wu    = (const float*)d_in[4];
    const float* bu    = (const float*)d_in[5];
    const float* Wg    = (const float*)d_in[6];
    const float* Wn    = (const float*)d_in[7];
    const float* dwk   = (const float*)d_in[8];
    const float* dwb   = (const float*)d_in[9];
    float* out = (float*)d_out;

    k_proj_down<<<Bb * KBLK, 256>>>(x, Wd, bd);
    k_gate<<<1, 32>>>(noise, Wg, Wn);
    k_conv_full<<<dim3(8, 24), 256>>>(dwk, dwb);
    k_expert_lo<<<dim3(24, 3), 256>>>(dwk, dwb);
    k_blend<<<384, 256>>>();
    k_proj_up<<<4736, 256>>>(x, Wu, bu, out);
}

// round 4
// speedup vs baseline: 1.2063x; 1.0173x over previous
#include <cuda_runtime.h>
#include <math.h>

#define Bb 8
#define Nn 16384
#define Dd 768
#define Rr 3
#define NEx 4
#define Hh 128
#define KBLK 64          // K1 blocks per batch
#define PLANE 16384      // floats per (b,r) plane
#define CHPLN 49152      // floats per batch (3 planes)
#define LO_PER_CH 5376   // 64*64 + 32*32 + 16*16

// ---- scratch (device globals; no allocations allowed) ----
__device__ float g_xr[Bb * Rr * PLANE];        // planar (B, R, N)
__device__ float g_mixed[Bb * Rr * PLANE];     // planar (B, R, N)
__device__ float g_lo[24 * LO_PER_CH];         // low-res conv outputs per channel
__device__ float g_partial[Bb * KBLK * 8 * 3]; // per-warp partial sums of xr
__device__ float g_G[Bb * NEx];                // gating weights

// ============================================================
// K1: xr = x @ Wd + bd. Per-warp cp.async rings, NO barriers in mainloop.
// grid = 512 blocks x 256 thr. Block: 256 tokens; warp w owns tokens w, w+8, ...
// Each lane copies and consumes exactly float4 slots (lane + 32*i).
// ============================================================
__device__ __forceinline__ void k1_issue_w(unsigned dstbase, const float4* src, int lane) {
#pragma unroll
    for (int i = 0; i < 6; ++i) {
        asm volatile("cp.async.cg.shared.global [%0], [%1], 16;\n"
                     :: "r"(dstbase + (unsigned)(lane + 32 * i) * 16u),
                        "l"(src + lane + 32 * i));
    }
    asm volatile("cp.async.commit_group;\n");
}

__global__ __launch_bounds__(256, 2) void k_proj_down(const float* __restrict__ x,
                                                      const float* __restrict__ Wd,
                                                      const float* __restrict__ bd) {
    __shared__ float buf[8][2][Dd];  // 48KB: per-warp double buffers
    const int b = blockIdx.x >> 6, blk = blockIdx.x & 63;
    const int tid = threadIdx.x, warp = tid >> 5, lane = tid & 31;

    // stage Wd through smem, pull per-lane weight slices into regs
    float* flat = &buf[0][0][0];
    for (int i = tid; i < Dd * Rr; i += 256) flat[i] = Wd[i];
    __syncthreads();
    float4 w0[6], w1[6], w2[6];
#pragma unroll
    for (int it = 0; it < 6; ++it) {
        int d = (lane + 32 * it) * 4;
        w0[it] = make_float4(flat[(d+0)*3+0], flat[(d+1)*3+0], flat[(d+2)*3+0], flat[(d+3)*3+0]);
        w1[it] = make_float4(flat[(d+0)*3+1], flat[(d+1)*3+1], flat[(d+2)*3+1], flat[(d+3)*3+1]);
        w2[it] = make_float4(flat[(d+0)*3+2], flat[(d+1)*3+2], flat[(d+2)*3+2], flat[(d+3)*3+2]);
    }
    const float b0 = bd[0], b1 = bd[1], b2 = bd[2];
    __syncthreads();

    const int token0 = blk * 256;
    const float4* base4 = (const float4*)x + (size_t)(b * Nn + token0 + warp) * 192;
    unsigned wbase = (unsigned)__cvta_generic_to_shared(&buf[warp][0][0]);

    k1_issue_w(wbase, base4, lane);
    k1_issue_w(wbase + Dd * 4, base4 + 1536, lane);

    float p0 = 0.f, p1 = 0.f, p2 = 0.f;
#pragma unroll 1
    for (int g = 0; g < 32; ++g) {
        if (g < 31) asm volatile("cp.async.wait_group 1;\n");
        else        asm volatile("cp.async.wait_group 0;\n");

        const float4* tb = (const float4*)&buf[warp][g & 1][0];
        float a0 = 0.f, a1 = 0.f, a2 = 0.f;
#pragma unroll
        for (int it = 0; it < 6; ++it) {
            float4 v = tb[lane + 32 * it];
            a0 += v.x*w0[it].x + v.y*w0[it].y + v.z*w0[it].z + v.w*w0[it].w;
            a1 += v.x*w1[it].x + v.y*w1[it].y + v.z*w1[it].z + v.w*w1[it].w;
            a2 += v.x*w2[it].x + v.y*w2[it].y + v.z*w2[it].z + v.w*w2[it].w;
        }
        // issue next group before the shuffle chain (independent of it)
        if (g + 2 < 32) k1_issue_w(wbase + (g & 1) * Dd * 4, base4 + (size_t)(g + 2) * 1536, lane);

#pragma unroll
        for (int off = 16; off; off >>= 1) {
            a0 += __shfl_xor_sync(0xffffffffu, a0, off);
            a1 += __shfl_xor_sync(0xffffffffu, a1, off);
            a2 += __shfl_xor_sync(0xffffffffu, a2, off);
        }
        if (lane == 0) {
            a0 += b0; a1 += b1; a2 += b2;
            int t = token0 + g * 8 + warp;
            g_xr[b * CHPLN + t]             = a0;
            g_xr[b * CHPLN + PLANE + t]     = a1;
            g_xr[b * CHPLN + 2 * PLANE + t] = a2;
            p0 += a0; p1 += a1; p2 += a2;
        }
    }
    if (lane == 0) {
        int pi = ((b * KBLK + blk) * 8 + warp) * 3;
        g_partial[pi] = p0; g_partial[pi + 1] = p1; g_partial[pi + 2] = p2;
    }
}

// ============================================================
// K2: gating. 1 block x 32 threads, fully deterministic.
// ============================================================
__global__ void k_gate(const float* __restrict__ noise,
                       const float* __restrict__ Wg,
                       const float* __restrict__ Wn) {
    __shared__ float sxa[Bb][Rr];
    const int t = threadIdx.x;
    if (t < Bb * Rr) {
        int b = t / 3, r = t % 3;
        float s = 0.f;
        for (int j = 0; j < KBLK * 8; ++j) s += g_partial[(b * KBLK * 8 + j) * 3 + r];
        sxa[b][r] = s * (1.0f / Nn);
    }
    __syncthreads();
    if (t < Bb) {
        float x0 = sxa[t][0], x1 = sxa[t][1], x2 = sxa[t][2];
        float hl[NEx];
#pragma unroll
        for (int e = 0; e < NEx; ++e) {
            float hg = x0 * Wg[e] + x1 * Wg[NEx + e] + x2 * Wg[2 * NEx + e];
            float z  = x0 * Wn[e] + x1 * Wn[NEx + e] + x2 * Wn[2 * NEx + e];
            float sp = fmaxf(z, 0.f) + log1pf(expf(-fabsf(z)));
            hl[e] = hg + noise[t * NEx + e] * sp;
        }
        int i1 = 0;
#pragma unroll
        for (int e = 1; e < NEx; ++e) if (hl[e] > hl[i1]) i1 = e;
        int i2 = -1;
#pragma unroll
        for (int e = 0; e < NEx; ++e) if (e != i1 && (i2 < 0 || hl[e] > hl[i2])) i2 = e;
        float e2  = expf(hl[i2] - hl[i1]);
        float inv = 1.f / (1.f + e2);
#pragma unroll
        for (int e = 0; e < NEx; ++e)
            g_G[t * NEx + e] = (e == i1) ? inv : ((e == i2) ? e2 * inv : 0.f);
    }
}

// ============================================================
// K3a: down (2-tap avg) + conv3x3 per (channel, scale) -> g_lo.
// grid (24, 3) x 256
// ============================================================
__global__ __launch_bounds__(256) void k_down_conv(const float* __restrict__ dwk,
                                                   const float* __restrict__ dwb) {
    __shared__ float sD[4096];
    __shared__ float sK[9];
    __shared__ float sBias;
    const int ch = blockIdx.x, r = ch % 3;
    const int sc = blockIdx.y + 1;
    if (threadIdx.x < 9) sK[threadIdx.x] = dwk[r * 9 + threadIdx.x];
    if (threadIdx.x == 9) sBias = dwb[r];
    __syncthreads();
    const int f = 1 << sc;
    const int m = 128 >> sc;
    const int o = (sc == 1) ? 0 : (sc == 2 ? 1 : 3);
    const float* __restrict__ A = g_xr + ch * PLANE;
    float* __restrict__ L = g_lo + ch * LO_PER_CH + ((sc == 1) ? 0 : (sc == 2 ? 4096 : 5120));

    for (int p = threadIdx.x; p < m * m; p += 256) {
        int i = p / m, j = p - i * m;
        const float* base = A + (f * i + o) * 128 + (f * j + o);
        sD[p] = 0.25f * (base[0] + base[1] + base[128] + base[129]);
    }
    __syncthreads();
    const float bias = sBias;
    for (int p = threadIdx.x; p < m * m; p += 256) {
        int i = p / m, j = p - i * m;
        float s = bias;
#pragma unroll
        for (int dy = -1; dy <= 1; ++dy) {
            int ii = i + dy;
            if (ii < 0 || ii >= m) continue;
#pragma unroll
            for (int dx = -1; dx <= 1; ++dx) {
                int jj = j + dx;
                if (jj < 0 || jj >= m) continue;
                s += sK[(dy + 1) * 3 + (dx + 1)] * sD[ii * m + jj];
            }
        }
        L[p] = s;
    }
}

// ============================================================
// K3b: fused full-res conv + 3 bilinear upsamples + G-blend -> g_mixed.
// grid (8 tiles, 24 channels) x 256
// ============================================================
template <int SC>
__device__ __forceinline__ float up_sample(const float* __restrict__ L, int oi, int oj) {
    constexpr int m = 128 >> SC;
    constexpr float invf = 1.0f / (float)(1 << SC);
    float sy = (oi + 0.5f) * invf - 0.5f;
    float sx = (oj + 0.5f) * invf - 0.5f;
    int y0 = (int)floorf(sy); float fy = sy - (float)y0;
    int x0 = (int)floorf(sx); float fx = sx - (float)x0;
    int y0c = max(y0, 0), y1c = min(y0 + 1, m - 1);
    int x0c = max(x0, 0), x1c = min(x0 + 1, m - 1);
    float v00 = __ldg(L + y0c * m + x0c), v01 = __ldg(L + y0c * m + x1c);
    float v10 = __ldg(L + y1c * m + x0c), v11 = __ldg(L + y1c * m + x1c);
    return (1.f - fy) * ((1.f - fx) * v00 + fx * v01)
         +        fy  * ((1.f - fx) * v10 + fx * v11);
}

__global__ __launch_bounds__(256) void k_up_blend(const float* __restrict__ dwk,
                                                  const float* __restrict__ dwb) {
    const int ch = blockIdx.y, b = ch / 3, r = ch - b * 3;
    __shared__ float sK[9];
    __shared__ float sc0[5];
    if (threadIdx.x < 9) sK[threadIdx.x] = dwk[r * 9 + threadIdx.x];
    if (threadIdx.x == 9) sc0[0] = dwb[r];
    if (threadIdx.x >= 10 && threadIdx.x < 14) sc0[1 + threadIdx.x - 10] = g_G[b * 4 + (threadIdx.x - 10)];
    __syncthreads();
    const float bias = sc0[0];
    const float g0 = sc0[1], g1 = sc0[2], g2 = sc0[3], g3 = sc0[4];
    const float* __restrict__ A  = g_xr + ch * PLANE;
    const float* __restrict__ L1 = g_lo + ch * LO_PER_CH;
    const float* __restrict__ L2p = L1 + 4096;
    const float* __restrict__ L3 = L1 + 5120;
    float* __restrict__ M = g_mixed + ch * PLANE;

    const int p0 = blockIdx.x * 2048;
    for (int p = p0 + threadIdx.x; p < p0 + 2048; p += 256) {
        int i = p >> 7, j = p & 127;
        float s = bias;
#pragma unroll
        for (int dy = -1; dy <= 1; ++dy) {
            int ii = i + dy;
            if (ii < 0 || ii > 127) continue;
#pragma unroll
            for (int dx = -1; dx <= 1; ++dx) {
                int jj = j + dx;
                if (jj < 0 || jj > 127) continue;
                s += sK[(dy + 1) * 3 + (dx + 1)] * A[ii * 128 + jj];
            }
        }
        float acc = g0 * s;
        acc += g1 * up_sample<1>(L1, i, j);
        acc += g2 * up_sample<2>(L2p, i, j);
        acc += g3 * up_sample<3>(L3, i, j);
        M[p] = acc;
    }
}

// ============================================================
// K4: out = x + mixed @ Wu + bu. 2 float4 per thread-iter. Streaming hints.
// ============================================================
__global__ __launch_bounds__(256) void k_proj_up(const float* __restrict__ x,
                                                 const float* __restrict__ Wu,
                                                 const float* __restrict__ bu,
                                                 float* __restrict__ out) {
    __shared__ float sW[Rr * Dd];
    __shared__ float sB[Dd];
    for (int i = threadIdx.x; i < Rr * Dd; i += 256) sW[i] = Wu[i];
    for (int i = threadIdx.x; i < Dd; i += 256) sB[i] = bu[i];
    __syncthreads();
    const int total = Bb * Nn * (Dd / 8);            // pairs of float4
    const int stride = gridDim.x * 256;
    for (int p = blockIdx.x * 256 + threadIdx.x; p < total; p += stride) {
        int tk = p / 96;                              // token (96 pairs/token)
        int q2 = (p - tk * 96) * 2;                   // float4 chunk within token
        int b  = tk >> 14;
        int t  = tk & (Nn - 1);
        const float* mp = g_mixed + b * CHPLN + t;
        float m0 = __ldg(mp), m1 = __ldg(mp + PLANE), m2 = __ldg(mp + 2 * PLANE);
        const float4* xp = (const float4*)x + (size_t)tk * 192 + q2;
        float4 xv0 = __ldcs(xp), xv1 = __ldcs(xp + 1);
        int d4 = q2 * 4;
        float4 a0 = *(const float4*)&sW[d4],          a0b = *(const float4*)&sW[d4 + 4];
        float4 a1 = *(const float4*)&sW[Dd + d4],     a1b = *(const float4*)&sW[Dd + d4 + 4];
        float4 a2 = *(const float4*)&sW[2*Dd + d4],   a2b = *(const float4*)&sW[2*Dd + d4 + 4];
        float4 bb = *(const float4*)&sB[d4],          bbb = *(const float4*)&sB[d4 + 4];
        float4 o0, o1;
        o0.x = xv0.x + bb.x + m0*a0.x + m1*a1.x + m2*a2.x;
        o0.y = xv0.y + bb.y + m0*a0.y + m1*a1.y + m2*a2.y;
        o0.z = xv0.z + bb.z + m0*a0.z + m1*a1.z + m2*a2.z;
        o0.w = xv0.w + bb.w + m0*a0.w + m1*a1.w + m2*a2.w;
        o1.x = xv1.x + bbb.x + m0*a0b.x + m1*a1b.x + m2*a2b.x;
        o1.y = xv1.y + bbb.y + m0*a0b.y + m1*a1b.y + m2*a2b.y;
        o1.z = xv1.z + bbb.z + m0*a0b.z + m1*a1b.z + m2*a2b.z;
        o1.w = xv1.w + bbb.w + m0*a0b.w + m1*a1b.w + m2*a2b.w;
        float4* op = (float4*)out + (size_t)tk * 192 + q2;
        __stcs(op, o0);
        __stcs(op + 1, o1);
    }
}

// ============================================================
// launch
// ============================================================
extern "C" void kernel_launch(void* const* d_in, const int* in_sizes, int n_in,
                              void* d_out, int out_size) {
    const float* x     = (const float*)d_in[0];
    const float* noise = (const float*)d_in[1];
    const float* Wd    = (const float*)d_in[2];
    const float* bd    = (const float*)d_in[3];
    const float* Wu    = (const float*)d_in[4];
    const float* bu    = (const float*)d_in[5];
    const float* Wg    = (const float*)d_in[6];
    const float* Wn    = (const float*)d_in[7];
    const float* dwk   = (const float*)d_in[8];
    const float* dwb   = (const float*)d_in[9];
    float* out = (float*)d_out;

    k_proj_down<<<Bb * KBLK, 256>>>(x, Wd, bd);
    k_gate<<<1, 32>>>(noise, Wg, Wn);
    k_down_conv<<<dim3(24, 3), 256>>>(dwk, dwb);
    k_up_blend<<<dim3(8, 24), 256>>>(dwk, dwb);
    k_proj_up<<<4736, 256>>>(x, Wu, bu, out);
}

// round 5
// speedup vs baseline: 1.2122x; 1.0049x over previous
#include <cuda_runtime.h>
#include <math.h>

#define Bb 8
#define Nn 16384
#define Dd 768
#define Rr 3
#define NEx 4
#define Hh 128
#define KBLK 64          // K1 blocks per batch
#define PLANE 16384      // floats per (b,r) plane
#define CHPLN 49152      // floats per batch (3 planes)

// ---- scratch (device globals; no allocations allowed) ----
__device__ float g_xr[Bb * Rr * PLANE];        // planar (B, R, N)
__device__ float g_mixed[Bb * Rr * PLANE];     // planar (B, R, N)
__device__ float g_partial[Bb * KBLK * 8 * 3]; // per-warp partial sums of xr
__device__ float g_G[Bb * NEx];                // gating weights

// ---- nop kernels: steer ncu capture slot onto k_proj_down ----
__global__ void k_nop() {}

// ============================================================
// K1: xr = x @ Wd + bd. Per-warp cp.async ring, DEPTH 4, issue-first.
// grid 512 x 256 thr, 96KB dynamic smem (8 warps x 4 slots x 3KB).
// Warp w owns tokens token0 + g*8 + w, g = 0..31.
// ============================================================
__device__ __forceinline__ void k1_issue(unsigned slotbase, const float4* src, int lane) {
#pragma unroll
    for (int i = 0; i < 6; ++i) {
        asm volatile("cp.async.cg.shared.global [%0], [%1], 16;\n"
                     :: "r"(slotbase + (unsigned)(lane + 32 * i) * 16u),
                        "l"(src + lane + 32 * i));
    }
    asm volatile("cp.async.commit_group;\n");
}

struct K1Acc { float p0, p1, p2; };

__device__ __forceinline__ void k1_compute(const float* slot, int lane,
                                           const float4* w0, const float4* w1, const float4* w2,
                                           float b0, float b1, float b2,
                                           int b, int t, K1Acc& acc) {
    const float4* tb = (const float4*)slot;
    float a0 = 0.f, a1 = 0.f, a2 = 0.f;
#pragma unroll
    for (int it = 0; it < 6; ++it) {
        float4 v = tb[lane + 32 * it];
        a0 += v.x*w0[it].x + v.y*w0[it].y + v.z*w0[it].z + v.w*w0[it].w;
        a1 += v.x*w1[it].x + v.y*w1[it].y + v.z*w1[it].z + v.w*w1[it].w;
        a2 += v.x*w2[it].x + v.y*w2[it].y + v.z*w2[it].z + v.w*w2[it].w;
    }
#pragma unroll
    for (int off = 16; off; off >>= 1) {
        a0 += __shfl_xor_sync(0xffffffffu, a0, off);
        a1 += __shfl_xor_sync(0xffffffffu, a1, off);
        a2 += __shfl_xor_sync(0xffffffffu, a2, off);
    }
    if (lane == 0) {
        a0 += b0; a1 += b1; a2 += b2;
        g_xr[b * CHPLN + t]             = a0;
        g_xr[b * CHPLN + PLANE + t]     = a1;
        g_xr[b * CHPLN + 2 * PLANE + t] = a2;
        acc.p0 += a0; acc.p1 += a1; acc.p2 += a2;
    }
}

__global__ __launch_bounds__(256, 2) void k_proj_down(const float* __restrict__ x,
                                                      const float* __restrict__ Wd,
                                                      const float* __restrict__ bd) {
    extern __shared__ float sbuf[];   // 8 * 4 * 768 floats = 96KB
    const int b = blockIdx.x >> 6, blk = blockIdx.x & 63;
    const int tid = threadIdx.x, warp = tid >> 5, lane = tid & 31;

    // stage Wd through smem, pull per-lane weight slices into regs
    for (int i = tid; i < Dd * Rr; i += 256) sbuf[i] = Wd[i];
    __syncthreads();
    float4 w0[6], w1[6], w2[6];
#pragma unroll
    for (int it = 0; it < 6; ++it) {
        int d = (lane + 32 * it) * 4;
        w0[it] = make_float4(sbuf[(d+0)*3+0], sbuf[(d+1)*3+0], sbuf[(d+2)*3+0], sbuf[(d+3)*3+0]);
        w1[it] = make_float4(sbuf[(d+0)*3+1], sbuf[(d+1)*3+1], sbuf[(d+2)*3+1], sbuf[(d+3)*3+1]);
        w2[it] = make_float4(sbuf[(d+0)*3+2], sbuf[(d+1)*3+2], sbuf[(d+2)*3+2], sbuf[(d+3)*3+2]);
    }
    const float b0 = bd[0], b1 = bd[1], b2 = bd[2];
    __syncthreads();

    const int token0 = blk * 256;
    const float4* base4 = (const float4*)x + (size_t)(b * Nn + token0 + warp) * 192;
    float* wslots = sbuf + warp * 4 * Dd;
    unsigned wbase = (unsigned)__cvta_generic_to_shared(wslots);

    // prologue: fill 3 slots
    k1_issue(wbase,              base4,            lane);
    k1_issue(wbase + 1u * 3072u, base4 + 1536,     lane);
    k1_issue(wbase + 2u * 3072u, base4 + 2 * 1536, lane);

    K1Acc acc = {0.f, 0.f, 0.f};
#pragma unroll 1
    for (int g = 0; g < 29; ++g) {
        // issue group g+3 into slot (g+3)&3 (consumed at iter g-1) BEFORE waiting
        k1_issue(wbase + (unsigned)((g + 3) & 3) * 3072u,
                 base4 + (size_t)(g + 3) * 1536, lane);
        asm volatile("cp.async.wait_group 3;\n");
        k1_compute(wslots + (g & 3) * Dd, lane, w0, w1, w2, b0, b1, b2,
                   b, token0 + g * 8 + warp, acc);
    }
    asm volatile("cp.async.wait_group 2;\n");
    k1_compute(wslots + (29 & 3) * Dd, lane, w0, w1, w2, b0, b1, b2,
               b, token0 + 29 * 8 + warp, acc);
    asm volatile("cp.async.wait_group 1;\n");
    k1_compute(wslots + (30 & 3) * Dd, lane, w0, w1, w2, b0, b1, b2,
               b, token0 + 30 * 8 + warp, acc);
    asm volatile("cp.async.wait_group 0;\n");
    k1_compute(wslots + (31 & 3) * Dd, lane, w0, w1, w2, b0, b1, b2,
               b, token0 + 31 * 8 + warp, acc);

    if (lane == 0) {
        int pi = ((b * KBLK + blk) * 8 + warp) * 3;
        g_partial[pi] = acc.p0; g_partial[pi + 1] = acc.p1; g_partial[pi + 2] = acc.p2;
    }
}

// ============================================================
// K2: gating. 1 block x 32 threads, fully deterministic.
// ============================================================
__global__ void k_gate(const float* __restrict__ noise,
                       const float* __restrict__ Wg,
                       const float* __restrict__ Wn) {
    __shared__ float sxa[Bb][Rr];
    const int t = threadIdx.x;
    if (t < Bb * Rr) {
        int b = t / 3, r = t % 3;
        float s = 0.f;
        for (int j = 0; j < KBLK * 8; ++j) s += g_partial[(b * KBLK * 8 + j) * 3 + r];
        sxa[b][r] = s * (1.0f / Nn);
    }
    __syncthreads();
    if (t < Bb) {
        float x0 = sxa[t][0], x1 = sxa[t][1], x2 = sxa[t][2];
        float hl[NEx];
#pragma unroll
        for (int e = 0; e < NEx; ++e) {
            float hg = x0 * Wg[e] + x1 * Wg[NEx + e] + x2 * Wg[2 * NEx + e];
            float z  = x0 * Wn[e] + x1 * Wn[NEx + e] + x2 * Wn[2 * NEx + e];
            float sp = fmaxf(z, 0.f) + log1pf(expf(-fabsf(z)));
            hl[e] = hg + noise[t * NEx + e] * sp;
        }
        int i1 = 0;
#pragma unroll
        for (int e = 1; e < NEx; ++e) if (hl[e] > hl[i1]) i1 = e;
        int i2 = -1;
#pragma unroll
        for (int e = 0; e < NEx; ++e) if (e != i1 && (i2 < 0 || hl[e] > hl[i2])) i2 = e;
        float e2  = expf(hl[i2] - hl[i1]);
        float inv = 1.f / (1.f + e2);
#pragma unroll
        for (int e = 0; e < NEx; ++e)
            g_G[t * NEx + e] = (e == i1) ? inv : ((e == i2) ? e2 * inv : 0.f);
    }
}

// ============================================================
// K3: fully fused experts. 24 blocks x 1024 thr, ~106KB dyn smem.
// sA plane -> downs(all scales) -> convs(all scales) ->
// fused full-res conv + 3 upsamples + blend -> g_mixed.
// sC layout: s1 @ 0 (64x64), s2 @ 4096 (32x32), s3 @ 5120 (16x16)
// ============================================================
template <int SC>
__device__ __forceinline__ float up_sample_s(const float* __restrict__ L, int oi, int oj) {
    constexpr int m = 128 >> SC;
    constexpr float invf = 1.0f / (float)(1 << SC);
    float sy = (oi + 0.5f) * invf - 0.5f;
    float sx = (oj + 0.5f) * invf - 0.5f;
    int y0 = (int)floorf(sy); float fy = sy - (float)y0;
    int x0 = (int)floorf(sx); float fx = sx - (float)x0;
    int y0c = max(y0, 0), y1c = min(y0 + 1, m - 1);
    int x0c = max(x0, 0), x1c = min(x0 + 1, m - 1);
    float v00 = L[y0c * m + x0c], v01 = L[y0c * m + x1c];
    float v10 = L[y1c * m + x0c], v11 = L[y1c * m + x1c];
    return (1.f - fy) * ((1.f - fx) * v00 + fx * v01)
         +        fy  * ((1.f - fx) * v10 + fx * v11);
}

__global__ __launch_bounds__(1024) void k_experts(const float* __restrict__ dwk,
                                                  const float* __restrict__ dwb) {
    extern __shared__ float sm[];
    float* sA = sm;            // 16384
    float* sC = sm + 16384;    // 5376
    float* sD = sm + 21760;    // 5376
    __shared__ float sK[9];
    __shared__ float sMeta[5];
    const int ch = blockIdx.x, b = ch / 3, r = ch - b * 3;
    const int tid = threadIdx.x;
    if (tid < 9) sK[tid] = dwk[r * 9 + tid];
    if (tid == 9) sMeta[0] = dwb[r];
    if (tid >= 10 && tid < 14) sMeta[1 + tid - 10] = g_G[b * 4 + (tid - 10)];

    // load plane (coalesced float4)
    const float4* Ap = (const float4*)(g_xr + ch * PLANE);
#pragma unroll
    for (int i = 0; i < 4; ++i) ((float4*)sA)[tid + 1024 * i] = Ap[tid + 1024 * i];
    __syncthreads();

    // downsample all scales: p in [0, 5376)
    for (int p = tid; p < 5376; p += 1024) {
        int m, off, o, f, idx;
        if (p < 4096)      { m = 64; off = 0;    o = 0; f = 2; idx = p; }
        else if (p < 5120) { m = 32; off = 4096; o = 1; f = 4; idx = p - 4096; }
        else               { m = 16; off = 5120; o = 3; f = 8; idx = p - 5120; }
        int i = idx / m, j = idx - i * m;
        const float* base = sA + (f * i + o) * 128 + (f * j + o);
        sD[off + idx] = 0.25f * (base[0] + base[1] + base[128] + base[129]);
    }
    __syncthreads();

    // conv all scales
    const float bias = sMeta[0];
    for (int p = tid; p < 5376; p += 1024) {
        int m, off, idx;
        if (p < 4096)      { m = 64; off = 0;    idx = p; }
        else if (p < 5120) { m = 32; off = 4096; idx = p - 4096; }
        else               { m = 16; off = 5120; idx = p - 5120; }
        int i = idx / m, j = idx - i * m;
        float s = bias;
        const float* Dp = sD + off;
#pragma unroll
        for (int dy = -1; dy <= 1; ++dy) {
            int ii = i + dy;
            if (ii < 0 || ii >= m) continue;
#pragma unroll
            for (int dx = -1; dx <= 1; ++dx) {
                int jj = j + dx;
                if (jj < 0 || jj >= m) continue;
                s += sK[(dy + 1) * 3 + (dx + 1)] * Dp[ii * m + jj];
            }
        }
        sC[off + idx] = s;
    }
    __syncthreads();

    // fused: full-res conv + 3 upsamples + blend
    const float g0 = sMeta[1], g1 = sMeta[2], g2 = sMeta[3], g3 = sMeta[4];
    float* __restrict__ M = g_mixed + ch * PLANE;
#pragma unroll
    for (int it = 0; it < 16; ++it) {
        int p = tid + 1024 * it;
        int i = p >> 7, j = p & 127;
        float s = bias;
#pragma unroll
        for (int dy = -1; dy <= 1; ++dy) {
            int ii = i + dy;
            if (ii < 0 || ii > 127) continue;
#pragma unroll
            for (int dx = -1; dx <= 1; ++dx) {
                int jj = j + dx;
                if (jj < 0 || jj > 127) continue;
                s += sK[(dy + 1) * 3 + (dx + 1)] * sA[ii * 128 + jj];
            }
        }
        float acc = g0 * s;
        acc += g1 * up_sample_s<1>(sC, i, j);
        acc += g2 * up_sample_s<2>(sC + 4096, i, j);
        acc += g3 * up_sample_s<3>(sC + 5120, i, j);
        M[p] = acc;
    }
}

// ============================================================
// K4: out = x + mixed @ Wu + bu. 2 float4 per thread-iter. Streaming hints.
// ============================================================
__global__ __launch_bounds__(256) void k_proj_up(const float* __restrict__ x,
                                                 const float* __restrict__ Wu,
                                                 const float* __restrict__ bu,
                                                 float* __restrict__ out) {
    __shared__ float sW[Rr * Dd];
    __shared__ float sB[Dd];
    for (int i = threadIdx.x; i < Rr * Dd; i += 256) sW[i] = Wu[i];
    for (int i = threadIdx.x; i < Dd; i += 256) sB[i] = bu[i];
    __syncthreads();
    const int total = Bb * Nn * (Dd / 8);            // pairs of float4
    const int stride = gridDim.x * 256;
    for (int p = blockIdx.x * 256 + threadIdx.x; p < total; p += stride) {
        int tk = p / 96;                              // token (96 pairs/token)
        int q2 = (p - tk * 96) * 2;                   // float4 chunk within token
        int b  = tk >> 14;
        int t  = tk & (Nn - 1);
        const float* mp = g_mixed + b * CHPLN + t;
        float m0 = __ldg(mp), m1 = __ldg(mp + PLANE), m2 = __ldg(mp + 2 * PLANE);
        const float4* xp = (const float4*)x + (size_t)tk * 192 + q2;
        float4 xv0 = __ldcs(xp), xv1 = __ldcs(xp + 1);
        int d4 = q2 * 4;
        float4 a0 = *(const float4*)&sW[d4],          a0b = *(const float4*)&sW[d4 + 4];
        float4 a1 = *(const float4*)&sW[Dd + d4],     a1b = *(const float4*)&sW[Dd + d4 + 4];
        float4 a2 = *(const float4*)&sW[2*Dd + d4],   a2b = *(const float4*)&sW[2*Dd + d4 + 4];
        float4 bb = *(const float4*)&sB[d4],          bbb = *(const float4*)&sB[d4 + 4];
        float4 o0, o1;
        o0.x = xv0.x + bb.x + m0*a0.x + m1*a1.x + m2*a2.x;
        o0.y = xv0.y + bb.y + m0*a0.y + m1*a1.y + m2*a2.y;
        o0.z = xv0.z + bb.z + m0*a0.z + m1*a1.z + m2*a2.z;
        o0.w = xv0.w + bb.w + m0*a0.w + m1*a1.w + m2*a2.w;
        o1.x = xv1.x + bbb.x + m0*a0b.x + m1*a1b.x + m2*a2b.x;
        o1.y = xv1.y + bbb.y + m0*a0b.y + m1*a1b.y + m2*a2b.y;
        o1.z = xv1.z + bbb.z + m0*a0b.z + m1*a1b.z + m2*a2b.z;
        o1.w = xv1.w + bbb.w + m0*a0b.w + m1*a1b.w + m2*a2b.w;
        float4* op = (float4*)out + (size_t)tk * 192 + q2;
        __stcs(op, o0);
        __stcs(op + 1, o1);
    }
}

// ============================================================
// launch
// ============================================================
extern "C" void kernel_launch(void* const* d_in, const int* in_sizes, int n_in,
                              void* d_out, int out_size) {
    const float* x     = (const float*)d_in[0];
    const float* noise = (const float*)d_in[1];
    const float* Wd    = (const float*)d_in[2];
    const float* bd    = (const float*)d_in[3];
    const float* Wu    = (const float*)d_in[4];
    const float* bu    = (const float*)d_in[5];
    const float* Wg    = (const float*)d_in[6];
    const float* Wn    = (const float*)d_in[7];
    const float* dwk   = (const float*)d_in[8];
    const float* dwb   = (const float*)d_in[9];
    float* out = (float*)d_out;

    cudaFuncSetAttribute(k_proj_down, cudaFuncAttributeMaxDynamicSharedMemorySize, 98304);
    cudaFuncSetAttribute(k_experts,   cudaFuncAttributeMaxDynamicSharedMemorySize, 108544);

    // 3 nops: steer ncu's capture slot (4th launch) onto k_proj_down
    k_nop<<<1, 32>>>();
    k_nop<<<1, 32>>>();
    k_nop<<<1, 32>>>();
    k_proj_down<<<Bb * KBLK, 256, 98304>>>(x, Wd, bd);
    k_gate<<<1, 32>>>(noise, Wg, Wn);
    k_experts<<<24, 1024, 108544>>>(dwk, dwb);
    k_proj_up<<<4736, 256>>>(x, Wu, bu, out);
}

// round 7
// speedup vs baseline: 1.3849x; 1.1425x over previous
#include <cuda_runtime.h>
#include <math.h>

#define Bb 8
#define Nn 16384
#define Dd 768
#define Rr 3
#define NEx 4
#define Hh 128
#define KBLK 64          // K1 blocks per batch
#define PLANE 16384      // floats per (b,r) plane
#define CHPLN 49152      // floats per batch (3 planes)

// ---- scratch (device globals; no allocations allowed) ----
__device__ float g_xr[Bb * Rr * PLANE];        // planar (B, R, N)
__device__ float g_mixed[Bb * Rr * PLANE];     // planar (B, R, N)
__device__ float g_partial[Bb * KBLK * 8 * 3]; // per-warp partial sums of xr
__device__ float g_G[Bb * NEx];                // gating weights

// ============================================================
// K1: xr = x @ Wd + bd. Per-warp cp.async ring, DEPTH 4, issue-first.
// grid 512 x 256 thr, 96KB dynamic smem (8 warps x 4 slots x 3KB).
// ============================================================
__device__ __forceinline__ void k1_issue(unsigned slotbase, const float4* src, int lane) {
#pragma unroll
    for (int i = 0; i < 6; ++i) {
        asm volatile("cp.async.cg.shared.global [%0], [%1], 16;\n"
                     :: "r"(slotbase + (unsigned)(lane + 32 * i) * 16u),
                        "l"(src + lane + 32 * i));
    }
    asm volatile("cp.async.commit_group;\n");
}

struct K1Acc { float p0, p1, p2; };

__device__ __forceinline__ void k1_compute(const float* slot, int lane,
                                           const float4* w0, const float4* w1, const float4* w2,
                                           float b0, float b1, float b2,
                                           int b, int t, K1Acc& acc) {
    const float4* tb = (const float4*)slot;
    float a0 = 0.f, a1 = 0.f, a2 = 0.f;
#pragma unroll
    for (int it = 0; it < 6; ++it) {
        float4 v = tb[lane + 32 * it];
        a0 += v.x*w0[it].x + v.y*w0[it].y + v.z*w0[it].z + v.w*w0[it].w;
        a1 += v.x*w1[it].x + v.y*w1[it].y + v.z*w1[it].z + v.w*w1[it].w;
        a2 += v.x*w2[it].x + v.y*w2[it].y + v.z*w2[it].z + v.w*w2[it].w;
    }
#pragma unroll
    for (int off = 16; off; off >>= 1) {
        a0 += __shfl_xor_sync(0xffffffffu, a0, off);
        a1 += __shfl_xor_sync(0xffffffffu, a1, off);
        a2 += __shfl_xor_sync(0xffffffffu, a2, off);
    }
    if (lane == 0) {
        a0 += b0; a1 += b1; a2 += b2;
        g_xr[b * CHPLN + t]             = a0;
        g_xr[b * CHPLN + PLANE + t]     = a1;
        g_xr[b * CHPLN + 2 * PLANE + t] = a2;
        acc.p0 += a0; acc.p1 += a1; acc.p2 += a2;
    }
}

__global__ __launch_bounds__(256, 2) void k_proj_down(const float* __restrict__ x,
                                                      const float* __restrict__ Wd,
                                                      const float* __restrict__ bd) {
    extern __shared__ float sbuf[];   // 8 * 4 * 768 floats = 96KB
    const int b = blockIdx.x >> 6, blk = blockIdx.x & 63;
    const int tid = threadIdx.x, warp = tid >> 5, lane = tid & 31;

    for (int i = tid; i < Dd * Rr; i += 256) sbuf[i] = Wd[i];
    __syncthreads();
    float4 w0[6], w1[6], w2[6];
#pragma unroll
    for (int it = 0; it < 6; ++it) {
        int d = (lane + 32 * it) * 4;
        w0[it] = make_float4(sbuf[(d+0)*3+0], sbuf[(d+1)*3+0], sbuf[(d+2)*3+0], sbuf[(d+3)*3+0]);
        w1[it] = make_float4(sbuf[(d+0)*3+1], sbuf[(d+1)*3+1], sbuf[(d+2)*3+1], sbuf[(d+3)*3+1]);
        w2[it] = make_float4(sbuf[(d+0)*3+2], sbuf[(d+1)*3+2], sbuf[(d+2)*3+2], sbuf[(d+3)*3+2]);
    }
    const float b0 = bd[0], b1 = bd[1], b2 = bd[2];
    __syncthreads();

    const int token0 = blk * 256;
    const float4* base4 = (const float4*)x + (size_t)(b * Nn + token0 + warp) * 192;
    float* wslots = sbuf + warp * 4 * Dd;
    unsigned wbase = (unsigned)__cvta_generic_to_shared(wslots);

    k1_issue(wbase,              base4,            lane);
    k1_issue(wbase + 1u * 3072u, base4 + 1536,     lane);
    k1_issue(wbase + 2u * 3072u, base4 + 2 * 1536, lane);

    K1Acc acc = {0.f, 0.f, 0.f};
#pragma unroll 1
    for (int g = 0; g < 29; ++g) {
        k1_issue(wbase + (unsigned)((g + 3) & 3) * 3072u,
                 base4 + (size_t)(g + 3) * 1536, lane);
        asm volatile("cp.async.wait_group 3;\n");
        k1_compute(wslots + (g & 3) * Dd, lane, w0, w1, w2, b0, b1, b2,
                   b, token0 + g * 8 + warp, acc);
    }
    asm volatile("cp.async.wait_group 2;\n");
    k1_compute(wslots + (29 & 3) * Dd, lane, w0, w1, w2, b0, b1, b2,
               b, token0 + 29 * 8 + warp, acc);
    asm volatile("cp.async.wait_group 1;\n");
    k1_compute(wslots + (30 & 3) * Dd, lane, w0, w1, w2, b0, b1, b2,
               b, token0 + 30 * 8 + warp, acc);
    asm volatile("cp.async.wait_group 0;\n");
    k1_compute(wslots + (31 & 3) * Dd, lane, w0, w1, w2, b0, b1, b2,
               b, token0 + 31 * 8 + warp, acc);

    if (lane == 0) {
        int pi = ((b * KBLK + blk) * 8 + warp) * 3;
        g_partial[pi] = acc.p0; g_partial[pi + 1] = acc.p1; g_partial[pi + 2] = acc.p2;
    }
}

// ============================================================
// K2: gating. 1 block x 32 threads, fully deterministic.
// ============================================================
__global__ void k_gate(const float* __restrict__ noise,
                       const float* __restrict__ Wg,
                       const float* __restrict__ Wn) {
    __shared__ float sxa[Bb][Rr];
    const int t = threadIdx.x;
    if (t < Bb * Rr) {
        int b = t / 3, r = t % 3;
        float s = 0.f;
        for (int j = 0; j < KBLK * 8; ++j) s += g_partial[(b * KBLK * 8 + j) * 3 + r];
        sxa[b][r] = s * (1.0f / Nn);
    }
    __syncthreads();
    if (t < Bb) {
        float x0 = sxa[t][0], x1 = sxa[t][1], x2 = sxa[t][2];
        float hl[NEx];
#pragma unroll
        for (int e = 0; e < NEx; ++e) {
            float hg = x0 * Wg[e] + x1 * Wg[NEx + e] + x2 * Wg[2 * NEx + e];
            float z  = x0 * Wn[e] + x1 * Wn[NEx + e] + x2 * Wn[2 * NEx + e];
            float sp = fmaxf(z, 0.f) + log1pf(expf(-fabsf(z)));
            hl[e] = hg + noise[t * NEx + e] * sp;
        }
        int i1 = 0;
#pragma unroll
        for (int e = 1; e < NEx; ++e) if (hl[e] > hl[i1]) i1 = e;
        int i2 = -1;
#pragma unroll
        for (int e = 0; e < NEx; ++e) if (e != i1 && (i2 < 0 || hl[e] > hl[i2])) i2 = e;
        float e2  = expf(hl[i2] - hl[i1]);
        float inv = 1.f / (1.f + e2);
#pragma unroll
        for (int e = 0; e < NEx; ++e)
            g_G[t * NEx + e] = (e == i1) ? inv : ((e == i2) ? e2 * inv : 0.f);
    }
}

// ============================================================
// K3: fully fused experts. 24 blocks x 1024 thr, ~106KB dyn smem.
// ============================================================
template <int SC>
__device__ __forceinline__ float up_sample_s(const float* __restrict__ L, int oi, int oj) {
    constexpr int m = 128 >> SC;
    constexpr float invf = 1.0f / (float)(1 << SC);
    float sy = (oi + 0.5f) * invf - 0.5f;
    float sx = (oj + 0.5f) * invf - 0.5f;
    int y0 = (int)floorf(sy); float fy = sy - (float)y0;
    int x0 = (int)floorf(sx); float fx = sx - (float)x0;
    int y0c = max(y0, 0), y1c = min(y0 + 1, m - 1);
    int x0c = max(x0, 0), x1c = min(x0 + 1, m - 1);
    float v00 = L[y0c * m + x0c], v01 = L[y0c * m + x1c];
    float v10 = L[y1c * m + x0c], v11 = L[y1c * m + x1c];
    return (1.f - fy) * ((1.f - fx) * v00 + fx * v01)
         +        fy  * ((1.f - fx) * v10 + fx * v11);
}

__global__ __launch_bounds__(1024) void k_experts(const float* __restrict__ dwk,
                                                  const float* __restrict__ dwb) {
    extern __shared__ float sm[];
    float* sA = sm;            // 16384
    float* sC = sm + 16384;    // 5376
    float* sD = sm + 21760;    // 5376
    __shared__ float sK[9];
    __shared__ float sMeta[5];
    const int ch = blockIdx.x, b = ch / 3, r = ch - b * 3;
    const int tid = threadIdx.x;
    if (tid < 9) sK[tid] = dwk[r * 9 + tid];
    if (tid == 9) sMeta[0] = dwb[r];
    if (tid >= 10 && tid < 14) sMeta[1 + tid - 10] = g_G[b * 4 + (tid - 10)];

    const float4* Ap = (const float4*)(g_xr + ch * PLANE);
#pragma unroll
    for (int i = 0; i < 4; ++i) ((float4*)sA)[tid + 1024 * i] = Ap[tid + 1024 * i];
    __syncthreads();

    for (int p = tid; p < 5376; p += 1024) {
        int m, off, o, f, idx;
        if (p < 4096)      { m = 64; off = 0;    o = 0; f = 2; idx = p; }
        else if (p < 5120) { m = 32; off = 4096; o = 1; f = 4; idx = p - 4096; }
        else               { m = 16; off = 5120; o = 3; f = 8; idx = p - 5120; }
        int i = idx / m, j = idx - i * m;
        const float* base = sA + (f * i + o) * 128 + (f * j + o);
        sD[off + idx] = 0.25f * (base[0] + base[1] + base[128] + base[129]);
    }
    __syncthreads();

    const float bias = sMeta[0];
    for (int p = tid; p < 5376; p += 1024) {
        int m, off, idx;
        if (p < 4096)      { m = 64; off = 0;    idx = p; }
        else if (p < 5120) { m = 32; off = 4096; idx = p - 4096; }
        else               { m = 16; off = 5120; idx = p - 5120; }
        int i = idx / m, j = idx - i * m;
        float s = bias;
        const float* Dp = sD + off;
#pragma unroll
        for (int dy = -1; dy <= 1; ++dy) {
            int ii = i + dy;
            if (ii < 0 || ii >= m) continue;
#pragma unroll
            for (int dx = -1; dx <= 1; ++dx) {
                int jj = j + dx;
                if (jj < 0 || jj >= m) continue;
                s += sK[(dy + 1) * 3 + (dx + 1)] * Dp[ii * m + jj];
            }
        }
        sC[off + idx] = s;
    }
    __syncthreads();

    const float g0 = sMeta[1], g1 = sMeta[2], g2 = sMeta[3], g3 = sMeta[4];
    float* __restrict__ M = g_mixed + ch * PLANE;
#pragma unroll
    for (int it = 0; it < 16; ++it) {
        int p = tid + 1024 * it;
        int i = p >> 7, j = p & 127;
        float s = bias;
#pragma unroll
        for (int dy = -1; dy <= 1; ++dy) {
            int ii = i + dy;
            if (ii < 0 || ii > 127) continue;
#pragma unroll
            for (int dx = -1; dx <= 1; ++dx) {
                int jj = j + dx;
                if (jj < 0 || jj > 127) continue;
                s += sK[(dy + 1) * 3 + (dx + 1)] * sA[ii * 128 + jj];
            }
        }
        float acc = g0 * s;
        acc += g1 * up_sample_s<1>(sC, i, j);
        acc += g2 * up_sample_s<2>(sC + 4096, i, j);
        acc += g3 * up_sample_s<3>(sC + 5120, i, j);
        M[p] = acc;
    }
}

// ============================================================
// K4: out = x + mixed @ Wu + bu. R2-proven shape: 1 float4/thread/iter,
// plain LDG/STG, smem weights; planar m via __ldg; unroll 4.
// ============================================================
__global__ __launch_bounds__(256) void k_proj_up(const float* __restrict__ x,
                                                 const float* __restrict__ Wu,
                                                 const float* __restrict__ bu,
                                                 float* __restrict__ out) {
    __shared__ float4 sW4[3 * 192];
    __shared__ float4 sB4[192];
    {
        float* sWf = (float*)sW4;
        float* sBf = (float*)sB4;
        for (int i = threadIdx.x; i < 3 * Dd; i += 256) sWf[i] = Wu[i];
        for (int i = threadIdx.x; i < Dd; i += 256) sBf[i] = bu[i];
    }
    __syncthreads();
    const int total = Bb * Nn * 192;          // float4 count
    const int stride = gridDim.x * 256;
#pragma unroll 4
    for (int p = blockIdx.x * 256 + threadIdx.x; p < total; p += stride) {
        int tk = p / 192;
        int q  = p - tk * 192;
        int b  = tk >> 14;
        int t  = tk & (Nn - 1);
        const float* mp = g_mixed + b * CHPLN + t;
        float m0 = __ldg(mp), m1 = __ldg(mp + PLANE), m2 = __ldg(mp + 2 * PLANE);
        float4 xv = ((const float4*)x)[p];
        float4 wu0 = sW4[q], wu1 = sW4[192 + q], wu2 = sW4[384 + q];
        float4 bb  = sB4[q];
        float4 ov;
        ov.x = xv.x + bb.x + m0 * wu0.x + m1 * wu1.x + m2 * wu2.x;
        ov.y = xv.y + bb.y + m0 * wu0.y + m1 * wu1.y + m2 * wu2.y;
        ov.z = xv.z + bb.z + m0 * wu0.z + m1 * wu1.z + m2 * wu2.z;
        ov.w = xv.w + bb.w + m0 * wu0.w + m1 * wu1.w + m2 * wu2.w;
        ((float4*)out)[p] = ov;
    }
}

// ============================================================
// launch (4 launches; ncu capture slot = 4th = k_proj_up)
// ============================================================
extern "C" void kernel_launch(void* const* d_in, const int* in_sizes, int n_in,
                              void* d_out, int out_size) {
    const float* x     = (const float*)d_in[0];
    const float* noise = (const float*)d_in[1];
    const float* Wd    = (const float*)d_in[2];
    const float* bd    = (const float*)d_in[3];
    const float* Wu    = (const float*)d_in[4];
    const float* bu    = (const float*)d_in[5];
    const float* Wg    = (const float*)d_in[6];
    const float* Wn    = (const float*)d_in[7];
    const float* dwk   = (const float*)d_in[8];
    const float* dwb   = (const float*)d_in[9];
    float* out = (float*)d_out;

    cudaFuncSetAttribute(k_proj_down, cudaFuncAttributeMaxDynamicSharedMemorySize, 98304);
    cudaFuncSetAttribute(k_experts,   cudaFuncAttributeMaxDynamicSharedMemorySize, 108544);

    k_proj_down<<<Bb * KBLK, 256, 98304>>>(x, Wd, bd);
    k_gate<<<1, 32>>>(noise, Wg, Wn);
    k_experts<<<24, 1024, 108544>>>(dwk, dwb);
    k_proj_up<<<4736, 256>>>(x, Wu, bu, out);
}

// round 8
// speedup vs baseline: 1.5602x; 1.1266x over previous
#include <cuda_runtime.h>
#include <math.h>

#define Bb 8
#define Nn 16384
#define Dd 768
#define Rr 3
#define NEx 4
#define Hh 128
#define KBLK 64          // K1 blocks per batch
#define PLANE 16384      // floats per (b,r) plane
#define CHPLN 49152      // floats per batch (3 planes)

// ---- scratch (device globals; no allocations allowed) ----
__device__ float g_xr[Bb * Rr * PLANE];        // planar (B, R, N)
__device__ float g_mixed[Bb * Rr * PLANE];     // planar (B, R, N)
__device__ float g_partial[Bb * KBLK * 8 * 3]; // per-warp partial sums of xr

// ============================================================
// K1: xr = x @ Wd + bd. Per-warp cp.async ring, DEPTH 4, issue-first.
// grid 512 x 256 thr, 96KB dynamic smem (8 warps x 4 slots x 3KB).
// ============================================================
__device__ __forceinline__ void k1_issue(unsigned slotbase, const float4* src, int lane) {
#pragma unroll
    for (int i = 0; i < 6; ++i) {
        asm volatile("cp.async.cg.shared.global [%0], [%1], 16;\n"
                     :: "r"(slotbase + (unsigned)(lane + 32 * i) * 16u),
                        "l"(src + lane + 32 * i));
    }
    asm volatile("cp.async.commit_group;\n");
}

struct K1Acc { float p0, p1, p2; };

__device__ __forceinline__ void k1_compute(const float* slot, int lane,
                                           const float4* w0, const float4* w1, const float4* w2,
                                           float b0, float b1, float b2,
                                           int b, int t, K1Acc& acc) {
    const float4* tb = (const float4*)slot;
    float a0 = 0.f, a1 = 0.f, a2 = 0.f;
#pragma unroll
    for (int it = 0; it < 6; ++it) {
        float4 v = tb[lane + 32 * it];
        a0 += v.x*w0[it].x + v.y*w0[it].y + v.z*w0[it].z + v.w*w0[it].w;
        a1 += v.x*w1[it].x + v.y*w1[it].y + v.z*w1[it].z + v.w*w1[it].w;
        a2 += v.x*w2[it].x + v.y*w2[it].y + v.z*w2[it].z + v.w*w2[it].w;
    }
#pragma unroll
    for (int off = 16; off; off >>= 1) {
        a0 += __shfl_xor_sync(0xffffffffu, a0, off);
        a1 += __shfl_xor_sync(0xffffffffu, a1, off);
        a2 += __shfl_xor_sync(0xffffffffu, a2, off);
    }
    if (lane == 0) {
        a0 += b0; a1 += b1; a2 += b2;
        g_xr[b * CHPLN + t]             = a0;
        g_xr[b * CHPLN + PLANE + t]     = a1;
        g_xr[b * CHPLN + 2 * PLANE + t] = a2;
        acc.p0 += a0; acc.p1 += a1; acc.p2 += a2;
    }
}

__global__ __launch_bounds__(256, 2) void k_proj_down(const float* __restrict__ x,
                                                      const float* __restrict__ Wd,
                                                      const float* __restrict__ bd) {
    extern __shared__ float sbuf[];   // 8 * 4 * 768 floats = 96KB
    const int b = blockIdx.x >> 6, blk = blockIdx.x & 63;
    const int tid = threadIdx.x, warp = tid >> 5, lane = tid & 31;

    for (int i = tid; i < Dd * Rr; i += 256) sbuf[i] = Wd[i];
    __syncthreads();
    float4 w0[6], w1[6], w2[6];
#pragma unroll
    for (int it = 0; it < 6; ++it) {
        int d = (lane + 32 * it) * 4;
        w0[it] = make_float4(sbuf[(d+0)*3+0], sbuf[(d+1)*3+0], sbuf[(d+2)*3+0], sbuf[(d+3)*3+0]);
        w1[it] = make_float4(sbuf[(d+0)*3+1], sbuf[(d+1)*3+1], sbuf[(d+2)*3+1], sbuf[(d+3)*3+1]);
        w2[it] = make_float4(sbuf[(d+0)*3+2], sbuf[(d+1)*3+2], sbuf[(d+2)*3+2], sbuf[(d+3)*3+2]);
    }
    const float b0 = bd[0], b1 = bd[1], b2 = bd[2];
    __syncthreads();

    const int token0 = blk * 256;
    const float4* base4 = (const float4*)x + (size_t)(b * Nn + token0 + warp) * 192;
    float* wslots = sbuf + warp * 4 * Dd;
    unsigned wbase = (unsigned)__cvta_generic_to_shared(wslots);

    k1_issue(wbase,              base4,            lane);
    k1_issue(wbase + 1u * 3072u, base4 + 1536,     lane);
    k1_issue(wbase + 2u * 3072u, base4 + 2 * 1536, lane);

    K1Acc acc = {0.f, 0.f, 0.f};
#pragma unroll 1
    for (int g = 0; g < 29; ++g) {
        k1_issue(wbase + (unsigned)((g + 3) & 3) * 3072u,
                 base4 + (size_t)(g + 3) * 1536, lane);
        asm volatile("cp.async.wait_group 3;\n");
        k1_compute(wslots + (g & 3) * Dd, lane, w0, w1, w2, b0, b1, b2,
                   b, token0 + g * 8 + warp, acc);
    }
    asm volatile("cp.async.wait_group 2;\n");
    k1_compute(wslots + (29 & 3) * Dd, lane, w0, w1, w2, b0, b1, b2,
               b, token0 + 29 * 8 + warp, acc);
    asm volatile("cp.async.wait_group 1;\n");
    k1_compute(wslots + (30 & 3) * Dd, lane, w0, w1, w2, b0, b1, b2,
               b, token0 + 30 * 8 + warp, acc);
    asm volatile("cp.async.wait_group 0;\n");
    k1_compute(wslots + (31 & 3) * Dd, lane, w0, w1, w2, b0, b1, b2,
               b, token0 + 31 * 8 + warp, acc);

    if (lane == 0) {
        int pi = ((b * KBLK + blk) * 8 + warp) * 3;
        g_partial[pi] = acc.p0; g_partial[pi + 1] = acc.p1; g_partial[pi + 2] = acc.p2;
    }
}

// ============================================================
// K3: fused experts + gating. grid (4 quadrants, 24 channels) x 1024.
// Every block: fixed-order gating reduction (identical across blocks of a
// batch -> deterministic), full low-res chain (cheap, duplicated x4),
// then its quadrant of full-res conv + 3 upsamples + blend.
// ============================================================
template <int SC>
__device__ __forceinline__ float up_sample_s(const float* __restrict__ L, int oi, int oj) {
    constexpr int m = 128 >> SC;
    constexpr float invf = 1.0f / (float)(1 << SC);
    float sy = (oi + 0.5f) * invf - 0.5f;
    float sx = (oj + 0.5f) * invf - 0.5f;
    int y0 = (int)floorf(sy); float fy = sy - (float)y0;
    int x0 = (int)floorf(sx); float fx = sx - (float)x0;
    int y0c = max(y0, 0), y1c = min(y0 + 1, m - 1);
    int x0c = max(x0, 0), x1c = min(x0 + 1, m - 1);
    float v00 = L[y0c * m + x0c], v01 = L[y0c * m + x1c];
    float v10 = L[y1c * m + x0c], v11 = L[y1c * m + x1c];
    return (1.f - fy) * ((1.f - fx) * v00 + fx * v01)
         +        fy  * ((1.f - fx) * v10 + fx * v11);
}

__global__ __launch_bounds__(1024) void k_experts(const float* __restrict__ dwk,
                                                  const float* __restrict__ dwb,
                                                  const float* __restrict__ noise,
                                                  const float* __restrict__ Wg,
                                                  const float* __restrict__ Wn) {
    extern __shared__ float sm[];
    float* sA = sm;            // 16384
    float* sC = sm + 16384;    // 5376
    float* sD = sm + 21760;    // 5376
    __shared__ float sred[3][512];
    __shared__ float sred2[3][64];
    __shared__ float sxa[3];
    __shared__ float sK[9];
    __shared__ float sMeta[5];
    const int q = blockIdx.x;                  // quadrant 0..3
    const int ch = blockIdx.y, b = ch / 3, r = ch - b * 3;
    const int tid = threadIdx.x;
    if (tid < 9) sK[tid] = dwk[r * 9 + tid];
    if (tid == 9) sMeta[0] = dwb[r];

    // gating partials
    if (tid < 512) {
        int base = (b * 512 + tid) * 3;
        sred[0][tid] = g_partial[base];
        sred[1][tid] = g_partial[base + 1];
        sred[2][tid] = g_partial[base + 2];
    }
    // load plane (coalesced float4)
    const float4* Ap = (const float4*)(g_xr + ch * PLANE);
#pragma unroll
    for (int i = 0; i < 4; ++i) ((float4*)sA)[tid + 1024 * i] = Ap[tid + 1024 * i];
    __syncthreads();

    // fixed-order reduction 512 -> 64 -> 8 -> 1 (identical in every block)
    if (tid < 192) {
        int a = tid >> 6, i = tid & 63;
        float s = 0.f;
#pragma unroll
        for (int k = 0; k < 8; ++k) s += sred[a][i * 8 + k];
        sred2[a][i] = s;
    }
    __syncthreads();
    if (tid < 24) {
        int a = tid >> 3, i = tid & 7;
        float s = 0.f;
#pragma unroll
        for (int k = 0; k < 8; ++k) s += sred2[a][i * 8 + k];
        sred[a][i] = s;   // reuse row head
    }
    __syncthreads();
    if (tid < 3) {
        float s = 0.f;
#pragma unroll
        for (int k = 0; k < 8; ++k) s += sred[tid][k];
        sxa[tid] = s * (1.0f / Nn);
    }
    __syncthreads();
    if (tid == 0) {
        float x0 = sxa[0], x1 = sxa[1], x2 = sxa[2];
        float hl[NEx];
#pragma unroll
        for (int e = 0; e < NEx; ++e) {
            float hg = x0 * Wg[e] + x1 * Wg[NEx + e] + x2 * Wg[2 * NEx + e];
            float z  = x0 * Wn[e] + x1 * Wn[NEx + e] + x2 * Wn[2 * NEx + e];
            float sp = fmaxf(z, 0.f) + log1pf(expf(-fabsf(z)));
            hl[e] = hg + noise[b * NEx + e] * sp;
        }
        int i1 = 0;
#pragma unroll
        for (int e = 1; e < NEx; ++e) if (hl[e] > hl[i1]) i1 = e;
        int i2 = -1;
#pragma unroll
        for (int e = 0; e < NEx; ++e) if (e != i1 && (i2 < 0 || hl[e] > hl[i2])) i2 = e;
        float e2  = expf(hl[i2] - hl[i1]);
        float inv = 1.f / (1.f + e2);
#pragma unroll
        for (int e = 0; e < NEx; ++e)
            sMeta[1 + e] = (e == i1) ? inv : ((e == i2) ? e2 * inv : 0.f);
    }

    // downsample all scales (full chain, duplicated across quadrants)
    for (int p = tid; p < 5376; p += 1024) {
        int m, off, o, f, idx;
        if (p < 4096)      { m = 64; off = 0;    o = 0; f = 2; idx = p; }
        else if (p < 5120) { m = 32; off = 4096; o = 1; f = 4; idx = p - 4096; }
        else               { m = 16; off = 5120; o = 3; f = 8; idx = p - 5120; }
        int i = idx / m, j = idx - i * m;
        const float* base = sA + (f * i + o) * 128 + (f * j + o);
        sD[off + idx] = 0.25f * (base[0] + base[1] + base[128] + base[129]);
    }
    __syncthreads();

    const float bias = sMeta[0];
    for (int p = tid; p < 5376; p += 1024) {
        int m, off, idx;
        if (p < 4096)      { m = 64; off = 0;    idx = p; }
        else if (p < 5120) { m = 32; off = 4096; idx = p - 4096; }
        else               { m = 16; off = 5120; idx = p - 5120; }
        int i = idx / m, j = idx - i * m;
        float s = bias;
        const float* Dp = sD + off;
#pragma unroll
        for (int dy = -1; dy <= 1; ++dy) {
            int ii = i + dy;
            if (ii < 0 || ii >= m) continue;
#pragma unroll
            for (int dx = -1; dx <= 1; ++dx) {
                int jj = j + dx;
                if (jj < 0 || jj >= m) continue;
                s += sK[(dy + 1) * 3 + (dx + 1)] * Dp[ii * m + jj];
            }
        }
        sC[off + idx] = s;
    }
    __syncthreads();

    // this quadrant's 32 rows: full-res conv + upsamples + blend
    const float g0 = sMeta[1], g1 = sMeta[2], g2 = sMeta[3], g3 = sMeta[4];
    float* __restrict__ M = g_mixed + ch * PLANE;
#pragma unroll
    for (int it = 0; it < 4; ++it) {
        int p = q * 4096 + tid + 1024 * it;
        int i = p >> 7, j = p & 127;
        float s = bias;
#pragma unroll
        for (int dy = -1; dy <= 1; ++dy) {
            int ii = i + dy;
            if (ii < 0 || ii > 127) continue;
#pragma unroll
            for (int dx = -1; dx <= 1; ++dx) {
                int jj = j + dx;
                if (jj < 0 || jj > 127) continue;
                s += sK[(dy + 1) * 3 + (dx + 1)] * sA[ii * 128 + jj];
            }
        }
        float acc = g0 * s;
        acc += g1 * up_sample_s<1>(sC, i, j);
        acc += g2 * up_sample_s<2>(sC + 4096, i, j);
        acc += g3 * up_sample_s<3>(sC + 5120, i, j);
        M[p] = acc;
    }
}

// ============================================================
// K4: out = x + mixed @ Wu + bu. R2-proven shape (measured 130us/74% DRAM).
// ============================================================
__global__ __launch_bounds__(256) void k_proj_up(const float* __restrict__ x,
                                                 const float* __restrict__ Wu,
                                                 const float* __restrict__ bu,
                                                 float* __restrict__ out) {
    __shared__ float4 sW4[3 * 192];
    __shared__ float4 sB4[192];
    {
        float* sWf = (float*)sW4;
        float* sBf = (float*)sB4;
        for (int i = threadIdx.x; i < 3 * Dd; i += 256) sWf[i] = Wu[i];
        for (int i = threadIdx.x; i < Dd; i += 256) sBf[i] = bu[i];
    }
    __syncthreads();
    const int total = Bb * Nn * 192;          // float4 count
    const int stride = gridDim.x * 256;
#pragma unroll 4
    for (int p = blockIdx.x * 256 + threadIdx.x; p < total; p += stride) {
        int tk = p / 192;
        int q  = p - tk * 192;
        int b  = tk >> 14;
        int t  = tk & (Nn - 1);
        const float* mp = g_mixed + b * CHPLN + t;
        float m0 = __ldg(mp), m1 = __ldg(mp + PLANE), m2 = __ldg(mp + 2 * PLANE);
        float4 xv = ((const float4*)x)[p];
        float4 wu0 = sW4[q], wu1 = sW4[192 + q], wu2 = sW4[384 + q];
        float4 bb  = sB4[q];
        float4 ov;
        ov.x = xv.x + bb.x + m0 * wu0.x + m1 * wu1.x + m2 * wu2.x;
        ov.y = xv.y + bb.y + m0 * wu0.y + m1 * wu1.y + m2 * wu2.y;
        ov.z = xv.z + bb.z + m0 * wu0.z + m1 * wu1.z + m2 * wu2.z;
        ov.w = xv.w + bb.w + m0 * wu0.w + m1 * wu1.w + m2 * wu2.w;
        ((float4*)out)[p] = ov;
    }
}

// ============================================================
// launch (3 launches)
// ============================================================
extern "C" void kernel_launch(void* const* d_in, const int* in_sizes, int n_in,
                              void* d_out, int out_size) {
    const float* x     = (const float*)d_in[0];
    const float* noise = (const float*)d_in[1];
    const float* Wd    = (const float*)d_in[2];
    const float* bd    = (const float*)d_in[3];
    const float* Wu    = (const float*)d_in[4];
    const float* bu    = (const float*)d_in[5];
    const float* Wg    = (const float*)d_in[6];
    const float* Wn    = (const float*)d_in[7];
    const float* dwk   = (const float*)d_in[8];
    const float* dwb   = (const float*)d_in[9];
    float* out = (float*)d_out;

    cudaFuncSetAttribute(k_proj_down, cudaFuncAttributeMaxDynamicSharedMemorySize, 98304);
    cudaFuncSetAttribute(k_experts,   cudaFuncAttributeMaxDynamicSharedMemorySize, 108544);

    k_proj_down<<<Bb * KBLK, 256, 98304>>>(x, Wd, bd);
    k_experts<<<dim3(4, 24), 1024, 108544>>>(dwk, dwb, noise, Wg, Wn);
    k_proj_up<<<4736, 256>>>(x, Wu, bu, out);
}

// round 9
// speedup vs baseline: 1.5838x; 1.0151x over previous
#include <cuda_runtime.h>
#include <math.h>

#define Bb 8
#define Nn 16384
#define Dd 768
#define Rr 3
#define NEx 4
#define Hh 128
#define KBLK 64          // K1 blocks per batch
#define PLANE 16384      // floats per (b,r) plane
#define CHPLN 49152      // floats per batch (3 planes)
#define K4GRID 4734      // 4734*256 divisible by 192 -> q invariant per thread

// ---- scratch (device globals; no allocations allowed) ----
__device__ float g_xr[Bb * Rr * PLANE];        // planar (B, R, N)
__device__ float g_mixed[Bb * Rr * PLANE];     // planar (B, R, N)
__device__ float g_partial[Bb * KBLK * 8 * 3]; // per-warp partial sums of xr

// ============================================================
// K1: xr = x @ Wd + bd. Per-warp cp.async ring, DEPTH 4, issue-first.
// (measured 67.3us @ 76.5% DRAM -- unchanged)
// ============================================================
__device__ __forceinline__ void k1_issue(unsigned slotbase, const float4* src, int lane) {
#pragma unroll
    for (int i = 0; i < 6; ++i) {
        asm volatile("cp.async.cg.shared.global [%0], [%1], 16;\n"
                     :: "r"(slotbase + (unsigned)(lane + 32 * i) * 16u),
                        "l"(src + lane + 32 * i));
    }
    asm volatile("cp.async.commit_group;\n");
}

struct K1Acc { float p0, p1, p2; };

__device__ __forceinline__ void k1_compute(const float* slot, int lane,
                                           const float4* w0, const float4* w1, const float4* w2,
                                           float b0, float b1, float b2,
                                           int b, int t, K1Acc& acc) {
    const float4* tb = (const float4*)slot;
    float a0 = 0.f, a1 = 0.f, a2 = 0.f;
#pragma unroll
    for (int it = 0; it < 6; ++it) {
        float4 v = tb[lane + 32 * it];
        a0 += v.x*w0[it].x + v.y*w0[it].y + v.z*w0[it].z + v.w*w0[it].w;
        a1 += v.x*w1[it].x + v.y*w1[it].y + v.z*w1[it].z + v.w*w1[it].w;
        a2 += v.x*w2[it].x + v.y*w2[it].y + v.z*w2[it].z + v.w*w2[it].w;
    }
#pragma unroll
    for (int off = 16; off; off >>= 1) {
        a0 += __shfl_xor_sync(0xffffffffu, a0, off);
        a1 += __shfl_xor_sync(0xffffffffu, a1, off);
        a2 += __shfl_xor_sync(0xffffffffu, a2, off);
    }
    if (lane == 0) {
        a0 += b0; a1 += b1; a2 += b2;
        g_xr[b * CHPLN + t]             = a0;
        g_xr[b * CHPLN + PLANE + t]     = a1;
        g_xr[b * CHPLN + 2 * PLANE + t] = a2;
        acc.p0 += a0; acc.p1 += a1; acc.p2 += a2;
    }
}

__global__ __launch_bounds__(256, 2) void k_proj_down(const float* __restrict__ x,
                                                      const float* __restrict__ Wd,
                                                      const float* __restrict__ bd) {
    extern __shared__ float sbuf[];   // 8 * 4 * 768 floats = 96KB
    const int b = blockIdx.x >> 6, blk = blockIdx.x & 63;
    const int tid = threadIdx.x, warp = tid >> 5, lane = tid & 31;

    for (int i = tid; i < Dd * Rr; i += 256) sbuf[i] = Wd[i];
    __syncthreads();
    float4 w0[6], w1[6], w2[6];
#pragma unroll
    for (int it = 0; it < 6; ++it) {
        int d = (lane + 32 * it) * 4;
        w0[it] = make_float4(sbuf[(d+0)*3+0], sbuf[(d+1)*3+0], sbuf[(d+2)*3+0], sbuf[(d+3)*3+0]);
        w1[it] = make_float4(sbuf[(d+0)*3+1], sbuf[(d+1)*3+1], sbuf[(d+2)*3+1], sbuf[(d+3)*3+1]);
        w2[it] = make_float4(sbuf[(d+0)*3+2], sbuf[(d+1)*3+2], sbuf[(d+2)*3+2], sbuf[(d+3)*3+2]);
    }
    const float b0 = bd[0], b1 = bd[1], b2 = bd[2];
    __syncthreads();

    const int token0 = blk * 256;
    const float4* base4 = (const float4*)x + (size_t)(b * Nn + token0 + warp) * 192;
    float* wslots = sbuf + warp * 4 * Dd;
    unsigned wbase = (unsigned)__cvta_generic_to_shared(wslots);

    k1_issue(wbase,              base4,            lane);
    k1_issue(wbase + 1u * 3072u, base4 + 1536,     lane);
    k1_issue(wbase + 2u * 3072u, base4 + 2 * 1536, lane);

    K1Acc acc = {0.f, 0.f, 0.f};
#pragma unroll 1
    for (int g = 0; g < 29; ++g) {
        k1_issue(wbase + (unsigned)((g + 3) & 3) * 3072u,
                 base4 + (size_t)(g + 3) * 1536, lane);
        asm volatile("cp.async.wait_group 3;\n");
        k1_compute(wslots + (g & 3) * Dd, lane, w0, w1, w2, b0, b1, b2,
                   b, token0 + g * 8 + warp, acc);
    }
    asm volatile("cp.async.wait_group 2;\n");
    k1_compute(wslots + (29 & 3) * Dd, lane, w0, w1, w2, b0, b1, b2,
               b, token0 + 29 * 8 + warp, acc);
    asm volatile("cp.async.wait_group 1;\n");
    k1_compute(wslots + (30 & 3) * Dd, lane, w0, w1, w2, b0, b1, b2,
               b, token0 + 30 * 8 + warp, acc);
    asm volatile("cp.async.wait_group 0;\n");
    k1_compute(wslots + (31 & 3) * Dd, lane, w0, w1, w2, b0, b1, b2,
               b, token0 + 31 * 8 + warp, acc);

    if (lane == 0) {
        int pi = ((b * KBLK + blk) * 8 + warp) * 3;
        g_partial[pi] = acc.p0; g_partial[pi + 1] = acc.p1; g_partial[pi + 2] = acc.p2;
    }
}

// ============================================================
// K3: fused experts + gating. grid (4 quadrants, 24 channels) x 1024.
// (unchanged from R8)
// ============================================================
template <int SC>
__device__ __forceinline__ float up_sample_s(const float* __restrict__ L, int oi, int oj) {
    constexpr int m = 128 >> SC;
    constexpr float invf = 1.0f / (float)(1 << SC);
    float sy = (oi + 0.5f) * invf - 0.5f;
    float sx = (oj + 0.5f) * invf - 0.5f;
    int y0 = (int)floorf(sy); float fy = sy - (float)y0;
    int x0 = (int)floorf(sx); float fx = sx - (float)x0;
    int y0c = max(y0, 0), y1c = min(y0 + 1, m - 1);
    int x0c = max(x0, 0), x1c = min(x0 + 1, m - 1);
    float v00 = L[y0c * m + x0c], v01 = L[y0c * m + x1c];
    float v10 = L[y1c * m + x0c], v11 = L[y1c * m + x1c];
    return (1.f - fy) * ((1.f - fx) * v00 + fx * v01)
         +        fy  * ((1.f - fx) * v10 + fx * v11);
}

__global__ __launch_bounds__(1024) void k_experts(const float* __restrict__ dwk,
                                                  const float* __restrict__ dwb,
                                                  const float* __restrict__ noise,
                                                  const float* __restrict__ Wg,
                                                  const float* __restrict__ Wn) {
    extern __shared__ float sm[];
    float* sA = sm;            // 16384
    float* sC = sm + 16384;    // 5376
    float* sD = sm + 21760;    // 5376
    __shared__ float sred[3][512];
    __shared__ float sred2[3][64];
    __shared__ float sxa[3];
    __shared__ float sK[9];
    __shared__ float sMeta[5];
    const int q = blockIdx.x;                  // quadrant 0..3
    const int ch = blockIdx.y, b = ch / 3, r = ch - b * 3;
    const int tid = threadIdx.x;
    if (tid < 9) sK[tid] = dwk[r * 9 + tid];
    if (tid == 9) sMeta[0] = dwb[r];

    if (tid < 512) {
        int base = (b * 512 + tid) * 3;
        sred[0][tid] = g_partial[base];
        sred[1][tid] = g_partial[base + 1];
        sred[2][tid] = g_partial[base + 2];
    }
    const float4* Ap = (const float4*)(g_xr + ch * PLANE);
#pragma unroll
    for (int i = 0; i < 4; ++i) ((float4*)sA)[tid + 1024 * i] = Ap[tid + 1024 * i];
    __syncthreads();

    if (tid < 192) {
        int a = tid >> 6, i = tid & 63;
        float s = 0.f;
#pragma unroll
        for (int k = 0; k < 8; ++k) s += sred[a][i * 8 + k];
        sred2[a][i] = s;
    }
    __syncthreads();
    if (tid < 24) {
        int a = tid >> 3, i = tid & 7;
        float s = 0.f;
#pragma unroll
        for (int k = 0; k < 8; ++k) s += sred2[a][i * 8 + k];
        sred[a][i] = s;
    }
    __syncthreads();
    if (tid < 3) {
        float s = 0.f;
#pragma unroll
        for (int k = 0; k < 8; ++k) s += sred[tid][k];
        sxa[tid] = s * (1.0f / Nn);
    }
    __syncthreads();
    if (tid == 0) {
        float x0 = sxa[0], x1 = sxa[1], x2 = sxa[2];
        float hl[NEx];
#pragma unroll
        for (int e = 0; e < NEx; ++e) {
            float hg = x0 * Wg[e] + x1 * Wg[NEx + e] + x2 * Wg[2 * NEx + e];
            float z  = x0 * Wn[e] + x1 * Wn[NEx + e] + x2 * Wn[2 * NEx + e];
            float sp = fmaxf(z, 0.f) + log1pf(expf(-fabsf(z)));
            hl[e] = hg + noise[b * NEx + e] * sp;
        }
        int i1 = 0;
#pragma unroll
        for (int e = 1; e < NEx; ++e) if (hl[e] > hl[i1]) i1 = e;
        int i2 = -1;
#pragma unroll
        for (int e = 0; e < NEx; ++e) if (e != i1 && (i2 < 0 || hl[e] > hl[i2])) i2 = e;
        float e2  = expf(hl[i2] - hl[i1]);
        float inv = 1.f / (1.f + e2);
#pragma unroll
        for (int e = 0; e < NEx; ++e)
            sMeta[1 + e] = (e == i1) ? inv : ((e == i2) ? e2 * inv : 0.f);
    }

    for (int p = tid; p < 5376; p += 1024) {
        int m, off, o, f, idx;
        if (p < 4096)      { m = 64; off = 0;    o = 0; f = 2; idx = p; }
        else if (p < 5120) { m = 32; off = 4096; o = 1; f = 4; idx = p - 4096; }
        else               { m = 16; off = 5120; o = 3; f = 8; idx = p - 5120; }
        int i = idx / m, j = idx - i * m;
        const float* base = sA + (f * i + o) * 128 + (f * j + o);
        sD[off + idx] = 0.25f * (base[0] + base[1] + base[128] + base[129]);
    }
    __syncthreads();

    const float bias = sMeta[0];
    for (int p = tid; p < 5376; p += 1024) {
        int m, off, idx;
        if (p < 4096)      { m = 64; off = 0;    idx = p; }
        else if (p < 5120) { m = 32; off = 4096; idx = p - 4096; }
        else               { m = 16; off = 5120; idx = p - 5120; }
        int i = idx / m, j = idx - i * m;
        float s = bias;
        const float* Dp = sD + off;
#pragma unroll
        for (int dy = -1; dy <= 1; ++dy) {
            int ii = i + dy;
            if (ii < 0 || ii >= m) continue;
#pragma unroll
            for (int dx = -1; dx <= 1; ++dx) {
                int jj = j + dx;
                if (jj < 0 || jj >= m) continue;
                s += sK[(dy + 1) * 3 + (dx + 1)] * Dp[ii * m + jj];
            }
        }
        sC[off + idx] = s;
    }
    __syncthreads();

    const float g0 = sMeta[1], g1 = sMeta[2], g2 = sMeta[3], g3 = sMeta[4];
    float* __restrict__ M = g_mixed + ch * PLANE;
#pragma unroll
    for (int it = 0; it < 4; ++it) {
        int p = q * 4096 + tid + 1024 * it;
        int i = p >> 7, j = p & 127;
        float s = bias;
#pragma unroll
        for (int dy = -1; dy <= 1; ++dy) {
            int ii = i + dy;
            if (ii < 0 || ii > 127) continue;
#pragma unroll
            for (int dx = -1; dx <= 1; ++dx) {
                int jj = j + dx;
                if (jj < 0 || jj > 127) continue;
                s += sK[(dy + 1) * 3 + (dx + 1)] * sA[ii * 128 + jj];
            }
        }
        float acc = g0 * s;
        acc += g1 * up_sample_s<1>(sC, i, j);
        acc += g2 * up_sample_s<2>(sC + 4096, i, j);
        acc += g3 * up_sample_s<3>(sC + 5120, i, j);
        M[p] = acc;
    }
}

// ============================================================
// K4: out = x + mixed @ Wu + bu. Register-invariant weights:
// stride divisible by 192 -> each thread's d-chunk q is FIXED across
// all iterations; wu/bias live in registers, zero smem in mainloop.
// ============================================================
__global__ __launch_bounds__(256) void k_proj_up(const float* __restrict__ x,
                                                 const float* __restrict__ Wu,
                                                 const float* __restrict__ bu,
                                                 float* __restrict__ out) {
    const int p0 = blockIdx.x * 256 + threadIdx.x;
    const int q  = p0 % 192;                  // fixed d-chunk for this thread
    const int d4 = q * 4;
    // loop-invariant weights in registers (L2/const-cached global reads)
    const float4 wu0 = __ldg((const float4*)(Wu + d4));
    const float4 wu1 = __ldg((const float4*)(Wu + Dd + d4));
    const float4 wu2 = __ldg((const float4*)(Wu + 2 * Dd + d4));
    const float4 bb  = __ldg((const float4*)(bu + d4));

    const int tkstep = (K4GRID * 256) / 192;  // 6312 tokens per iteration step
    const int ntok = Bb * Nn;
#pragma unroll 4
    for (int tk = p0 / 192; tk < ntok; tk += tkstep) {
        int b = tk >> 14;
        int t = tk & (Nn - 1);
        const float* mp = g_mixed + b * CHPLN + t;
        float m0 = __ldg(mp), m1 = __ldg(mp + PLANE), m2 = __ldg(mp + 2 * PLANE);
        int p = tk * 192 + q;
        float4 xv = ((const float4*)x)[p];
        float4 ov;
        ov.x = xv.x + bb.x + m0 * wu0.x + m1 * wu1.x + m2 * wu2.x;
        ov.y = xv.y + bb.y + m0 * wu0.y + m1 * wu1.y + m2 * wu2.y;
        ov.z = xv.z + bb.z + m0 * wu0.z + m1 * wu1.z + m2 * wu2.z;
        ov.w = xv.w + bb.w + m0 * wu0.w + m1 * wu1.w + m2 * wu2.w;
        ((float4*)out)[p] = ov;
    }
}

// ============================================================
// launch (3 launches)
// ============================================================
extern "C" void kernel_launch(void* const* d_in, const int* in_sizes, int n_in,
                              void* d_out, int out_size) {
    const float* x     = (const float*)d_in[0];
    const float* noise = (const float*)d_in[1];
    const float* Wd    = (const float*)d_in[2];
    const float* bd    = (const float*)d_in[3];
    const float* Wu    = (const float*)d_in[4];
    const float* bu    = (const float*)d_in[5];
    const float* Wg    = (const float*)d_in[6];
    const float* Wn    = (const float*)d_in[7];
    const float* dwk   = (const float*)d_in[8];
    const float* dwb   = (const float*)d_in[9];
    float* out = (float*)d_out;

    cudaFuncSetAttribute(k_proj_down, cudaFuncAttributeMaxDynamicSharedMemorySize, 98304);
    cudaFuncSetAttribute(k_experts,   cudaFuncAttributeMaxDynamicSharedMemorySize, 108544);

    k_proj_down<<<Bb * KBLK, 256, 98304>>>(x, Wd, bd);
    k_experts<<<dim3(4, 24), 1024, 108544>>>(dwk, dwb, noise, Wg, Wn);
    k_proj_up<<<K4GRID, 256>>>(x, Wu, bu, out);
}